// round 11
// baseline (speedup 1.0000x reference)
#include <cuda_runtime.h>
#include <cuda_bf16.h>
#include <cstdint>
#include <cmath>

// Problem constants (match reference_code)
#define NN     50000
#define NNP    50048   // NN padded to multiple of 128 (frag-ordered A arrays)
#define EE     800000
#define ETOT   (NN + EE)
#define IND    256
#define HIDD   64
#define NHEADS 4
#define D1     256
#define D2     64
#define NEG_SLOPE 0.2f

// ---------------------------------------------------------------------------
// Scratch.  g_xh/g_xl/g_hrh/g_hrl are stored in MMA-FRAGMENT ORDER:
//   block (rb, kb) of 16x16; within block: lane = ((r&7)<<2)|((c&7)>>1),
//   q = ((r>>3)&1)|(((c>>3)&1)<<1), elem = c&1;
//   offset = (rb*(K/16)+kb)*256 + lane*8 + q*2 + elem.
// One warp frag = one coalesced 16B/lane LDG.
// ---------------------------------------------------------------------------
__device__ __align__(16) float g_h1[(size_t)NN * D1];
__device__ __align__(16) float g_h2[(size_t)NN * D2];
__device__ __align__(16) __nv_bfloat16 g_xh[(size_t)NNP * IND];   // frag order
__device__ __align__(16) __nv_bfloat16 g_xl[(size_t)NNP * IND];   // frag order
__device__ __align__(16) __nv_bfloat16 g_w1h[IND * D1];           // flat
__device__ __align__(16) __nv_bfloat16 g_w1l[IND * D1];
__device__ __align__(16) __nv_bfloat16 g_w2h[D1 * D2];
__device__ __align__(16) __nv_bfloat16 g_w2l[D1 * D2];
__device__ __align__(16) __nv_bfloat16 g_hrh[(size_t)NNP * D1];   // frag order
__device__ __align__(16) __nv_bfloat16 g_hrl[(size_t)NNP * D1];   // frag order
__device__ __align__(16) float g_as1[NN * NHEADS];
__device__ __align__(16) float g_ad1[NN * NHEADS];
__device__ __align__(16) float g_as2[NN];
__device__ __align__(16) float g_ad2[NN];
__device__ int   g_deg[NN];
__device__ int   g_row[NN + 1];
__device__ int   g_cur[NN];
__device__ int   g_csr[ETOT];
__device__ int   g_bsum[64];
__device__ int   g_boff[64];

// ---------------------------------------------------------------------------
// PTX helpers
// ---------------------------------------------------------------------------
__device__ __forceinline__ uint32_t sptr(const void* p) {
    return (uint32_t)__cvta_generic_to_shared(p);
}
__device__ __forceinline__ void ldsm4t(uint32_t* r, uint32_t a) {
    asm volatile("ldmatrix.sync.aligned.m8n8.x4.trans.shared.b16 {%0,%1,%2,%3}, [%4];"
                 : "=r"(r[0]), "=r"(r[1]), "=r"(r[2]), "=r"(r[3]) : "r"(a));
}
__device__ __forceinline__ void mma16816(float* c, const uint32_t* a, const uint32_t* b) {
    asm volatile(
        "mma.sync.aligned.m16n8k16.row.col.f32.bf16.bf16.f32 "
        "{%0,%1,%2,%3},{%4,%5,%6,%7},{%8,%9},{%0,%1,%2,%3};"
        : "+f"(c[0]), "+f"(c[1]), "+f"(c[2]), "+f"(c[3])
        : "r"(a[0]), "r"(a[1]), "r"(a[2]), "r"(a[3]), "r"(b[0]), "r"(b[1]));
}

// ---------------------------------------------------------------------------
// Fused split: x -> frag-ordered bf16 hi/lo; W1/W2 -> flat bf16 hi/lo
// ---------------------------------------------------------------------------
__global__ void split_all_kernel(const float* __restrict__ x,
                                 const float* __restrict__ W1,
                                 const float* __restrict__ W2, int n)
{
    const int xw = n * 32;                 // 8 elems per item
    constexpr int W1_4 = IND * D1 / 4;
    constexpr int W2_4 = D1 * D2 / 4;
    const int i = blockIdx.x * blockDim.x + threadIdx.x;

    if (i < xw) {
        const int r  = i >> 5;
        const int c0 = (i & 31) << 3;
        const float4 v0 = *reinterpret_cast<const float4*>(x + (size_t)r * IND + c0);
        const float4 v1 = *reinterpret_cast<const float4*>(x + (size_t)r * IND + c0 + 4);
        const float vv[8] = {v0.x, v0.y, v0.z, v0.w, v1.x, v1.y, v1.z, v1.w};
        const int rb = r >> 4, kb = c0 >> 4;
        const int q  = ((r >> 3) & 1) | (((c0 >> 3) & 1) << 1);
        const size_t base = ((size_t)(rb * (IND / 16) + kb)) * 256
                          + ((r & 7) << 2) * 8 + q * 2;
#pragma unroll
        for (int t = 0; t < 4; t++) {
            const __nv_bfloat16 h0 = __float2bfloat16(vv[2 * t]);
            const __nv_bfloat16 h1 = __float2bfloat16(vv[2 * t + 1]);
            const __nv_bfloat16 l0 = __float2bfloat16(vv[2 * t] - __bfloat162float(h0));
            const __nv_bfloat16 l1 = __float2bfloat16(vv[2 * t + 1] - __bfloat162float(h1));
            *reinterpret_cast<__nv_bfloat162*>(g_xh + base + t * 8) = __nv_bfloat162{h0, h1};
            *reinterpret_cast<__nv_bfloat162*>(g_xl + base + t * 8) = __nv_bfloat162{l0, l1};
        }
        return;
    }

    int j = i - xw;
    const float* src;
    __nv_bfloat16 *hi, *lo;
    if (j < W1_4)             { src = W1; hi = g_w1h; lo = g_w1l; }
    else if (j < W1_4 + W2_4) { j -= W1_4; src = W2; hi = g_w2h; lo = g_w2l; }
    else return;

    const float4 v = reinterpret_cast<const float4*>(src)[j];
    const float vv[4] = {v.x, v.y, v.z, v.w};
    __nv_bfloat16 h[4], l[4];
#pragma unroll
    for (int q = 0; q < 4; q++) {
        h[q] = __float2bfloat16(vv[q]);
        l[q] = __float2bfloat16(vv[q] - __bfloat162float(h[q]));
    }
    reinterpret_cast<__nv_bfloat162*>(hi)[2 * j + 0] = __nv_bfloat162{h[0], h[1]};
    reinterpret_cast<__nv_bfloat162*>(hi)[2 * j + 1] = __nv_bfloat162{h[2], h[3]};
    reinterpret_cast<__nv_bfloat162*>(lo)[2 * j + 0] = __nv_bfloat162{l[0], l[1]};
    reinterpret_cast<__nv_bfloat162*>(lo)[2 * j + 1] = __nv_bfloat162{l[2], l[3]};
}

// ---------------------------------------------------------------------------
// Zero: g_deg + all atomically-accumulated alpha dots
// ---------------------------------------------------------------------------
__global__ void zero_all_kernel(int n)
{
    const int i = blockIdx.x * blockDim.x + threadIdx.x;
    if (i < n) {
        g_deg[i] = 0;
        g_as2[i] = 0.f;
        g_ad2[i] = 0.f;
    }
    if (i < n * NHEADS) {
        g_as1[i] = 0.f;
        g_ad1[i] = 0.f;
    }
}

// ---------------------------------------------------------------------------
// Tensor-core GEMM (bf16 3-term split), 128x64 tile, 2 CTAs/SM.
// A fragments loaded DIRECTLY from frag-ordered global (no smem/ldsm for A).
// B (weights) staged through smem + ldsm4t as before.
// Fused alpha-dot epilogue (atomicAdd partial sums).
// ---------------------------------------------------------------------------
template <int LAYER>
__global__ void __launch_bounds__(256, 2)
mma_gemm_kernel(int M, const float* __restrict__ avec_s,
                const float* __restrict__ avec_d)
{
    constexpr int K  = 256;
    constexpr int N  = (LAYER == 1) ? D1 : D2;
    constexpr int BN = 64;
    constexpr int BM = 128;
    constexpr int BK = 32;
    constexpr int NP = BN + 8;
    constexpr int NT = 4;

    const __nv_bfloat16* __restrict__ Ah = (LAYER == 1) ? g_xh  : g_hrh;
    const __nv_bfloat16* __restrict__ Al = (LAYER == 1) ? g_xl  : g_hrl;
    const __nv_bfloat16* __restrict__ Bh = (LAYER == 1) ? g_w1h : g_w2h;
    const __nv_bfloat16* __restrict__ Bl = (LAYER == 1) ? g_w1l : g_w2l;
    float* __restrict__ C                = (LAYER == 1) ? g_h1  : g_h2;
    float* __restrict__ as_out           = (LAYER == 1) ? g_as1 : g_as2;
    float* __restrict__ ad_out           = (LAYER == 1) ? g_ad1 : g_ad2;

    __shared__ __align__(16) __nv_bfloat16 sBh[BK][NP], sBl[BK][NP];

    const int tid  = threadIdx.x;
    const int lane = tid & 31;
    const int wid  = tid >> 5;
    const int wm   = (wid & 3) * 32;
    const int wn   = (wid >> 2) * 32;
    const int brow = blockIdx.y * BM;
    const int bcol = blockIdx.x * BN;

    // B loader: 32x64 = 256 uint4 slots, 1 hi + 1 lo per thread
    const int bkr = tid >> 3;
    const int bnc = (tid & 7) * 8;

    uint4 ub_h, ub_l;
    auto gloadB = [&](int k0) {
        const size_t off = (size_t)(k0 + bkr) * N + bcol + bnc;
        ub_h = *reinterpret_cast<const uint4*>(Bh + off);
        ub_l = *reinterpret_cast<const uint4*>(Bl + off);
    };
    auto sstoreB = [&]() {
        *reinterpret_cast<uint4*>(&sBh[bkr][bnc]) = ub_h;
        *reinterpret_cast<uint4*>(&sBl[bkr][bnc]) = ub_l;
    };

    // A fragment regs: [ks][ifrag], hi and lo (frag-ordered global loads)
    uint4 uah[2][2], ual[2][2];
    auto aload = [&](int kt) {
#pragma unroll
        for (int ks = 0; ks < 2; ks++)
#pragma unroll
            for (int i = 0; i < 2; i++) {
                const int rb = (brow + wm + i * 16) >> 4;
                const int kb = kt * 2 + ks;
                const size_t off = ((size_t)(rb * (K / 16) + kb)) * 256 + lane * 8;
                uah[ks][i] = *reinterpret_cast<const uint4*>(Ah + off);
                ual[ks][i] = *reinterpret_cast<const uint4*>(Al + off);
            }
    };

    float c[2][NT][4];
#pragma unroll
    for (int i = 0; i < 2; i++)
#pragma unroll
        for (int j = 0; j < NT; j++)
#pragma unroll
            for (int q = 0; q < 4; q++) c[i][j][q] = 0.f;

    gloadB(0);
    sstoreB();
    aload(0);
    __syncthreads();

    constexpr int NKT = K / BK;   // 8
    for (int kt = 0; kt < NKT; kt++) {
        if (kt + 1 < NKT) gloadB((kt + 1) * BK);

#pragma unroll
        for (int ks = 0; ks < 2; ks++) {
            const int k16 = ks * 16;
            uint32_t fb_h[NT][2], fb_l[NT][2];
#pragma unroll
            for (int j = 0; j < NT / 2; j++) {
                const int rr = k16 + (lane & 15);
                const int cc = wn + j * 16 + 8 * (lane >> 4);
                uint32_t t[4];
                ldsm4t(t, sptr(&sBh[rr][cc]));
                fb_h[2 * j][0] = t[0]; fb_h[2 * j][1] = t[1];
                fb_h[2 * j + 1][0] = t[2]; fb_h[2 * j + 1][1] = t[3];
                ldsm4t(t, sptr(&sBl[rr][cc]));
                fb_l[2 * j][0] = t[0]; fb_l[2 * j][1] = t[1];
                fb_l[2 * j + 1][0] = t[2]; fb_l[2 * j + 1][1] = t[3];
            }
#pragma unroll
            for (int i = 0; i < 2; i++) {
                const uint32_t* fah = reinterpret_cast<const uint32_t*>(&uah[ks][i]);
                const uint32_t* fal = reinterpret_cast<const uint32_t*>(&ual[ks][i]);
#pragma unroll
                for (int j = 0; j < NT; j++) {
                    mma16816(c[i][j], fah, fb_h[j]);
                    mma16816(c[i][j], fah, fb_l[j]);
                    mma16816(c[i][j], fal, fb_h[j]);
                }
            }
        }

        __syncthreads();
        if (kt + 1 < NKT) {
            sstoreB();
            aload(kt + 1);     // prefetch next ktile's A frags
            __syncthreads();
        }
    }

    // ---- epilogue: store C + fused (partial) alpha dots ----
    const int head = (LAYER == 1) ? (bcol >> 6) : 0;
#pragma unroll
    for (int i = 0; i < 2; i++) {
        float s0 = 0.f, s1 = 0.f, d0 = 0.f, d1 = 0.f;
#pragma unroll
        for (int j = 0; j < NT; j++) {
            const int col = bcol + wn + j * 8 + (lane & 3) * 2;
            const float a0 = __ldg(avec_s + col), a1 = __ldg(avec_s + col + 1);
            const float b0 = __ldg(avec_d + col), b1 = __ldg(avec_d + col + 1);
            s0 += c[i][j][0] * a0 + c[i][j][1] * a1;
            s1 += c[i][j][2] * a0 + c[i][j][3] * a1;
            d0 += c[i][j][0] * b0 + c[i][j][1] * b1;
            d1 += c[i][j][2] * b0 + c[i][j][3] * b1;

            const int r = brow + wm + i * 16 + (lane >> 2);
            if (r < M)
                *reinterpret_cast<float2*>(C + (size_t)r * N + col) =
                    make_float2(c[i][j][0], c[i][j][1]);
            if (r + 8 < M)
                *reinterpret_cast<float2*>(C + (size_t)(r + 8) * N + col) =
                    make_float2(c[i][j][2], c[i][j][3]);
        }
#pragma unroll
        for (int off = 1; off <= 2; off <<= 1) {
            s0 += __shfl_xor_sync(0xffffffffu, s0, off);
            s1 += __shfl_xor_sync(0xffffffffu, s1, off);
            d0 += __shfl_xor_sync(0xffffffffu, d0, off);
            d1 += __shfl_xor_sync(0xffffffffu, d1, off);
        }
        if ((lane & 3) == 0) {
            const int r = brow + wm + i * 16 + (lane >> 2);
            const int stride = (LAYER == 1) ? NHEADS : 1;
            if (r < M) {
                atomicAdd(&as_out[r * stride + head], s0);
                atomicAdd(&ad_out[r * stride + head], d0);
            }
            if (r + 8 < M) {
                atomicAdd(&as_out[(r + 8) * stride + head], s1);
                atomicAdd(&ad_out[(r + 8) * stride + head], d1);
            }
        }
    }
}

// ---------------------------------------------------------------------------
// CSR build
// ---------------------------------------------------------------------------
__global__ void hist_kernel(const int* __restrict__ ei, int E, int n)
{
    const int i = blockIdx.x * blockDim.x + threadIdx.x;
    const int tot = E + n;
    if (i >= tot) return;
    const int d = (i < E) ? ei[E + i] : (i - E);
    if ((unsigned)d < (unsigned)n)
        atomicAdd(&g_deg[d], 1);
}

__global__ void scan1_kernel(int n)
{
    __shared__ int smem[1024];
    const int tid = threadIdx.x;
    const int i = blockIdx.x * 1024 + tid;
    const int v = (i < n) ? g_deg[i] : 0;
    int x = v;
#pragma unroll
    for (int off = 1; off < 1024; off <<= 1) {
        smem[tid] = x;
        __syncthreads();
        if (tid >= off) x += smem[tid - off];
        __syncthreads();
    }
    if (i < n) g_row[i] = x - v;
    if (tid == 1023) g_bsum[blockIdx.x] = x;
}

__global__ void scan2_kernel(int nb, int n)
{
    __shared__ int sm[64];
    const int tid = threadIdx.x;
    const int v = (tid < nb) ? g_bsum[tid] : 0;
    int x = v;
#pragma unroll
    for (int off = 1; off < 64; off <<= 1) {
        sm[tid] = x;
        __syncthreads();
        if (tid >= off) x += sm[tid - off];
        __syncthreads();
    }
    if (tid < nb) g_boff[tid] = x - v;
    if (tid == 63) g_row[n] = x;
}

__global__ void scan3_kernel(int n)
{
    const int i = blockIdx.x * blockDim.x + threadIdx.x;
    if (i >= n) return;
    const int v = g_row[i] + g_boff[i >> 10];
    g_row[i] = v;
    g_cur[i] = v;
}

__global__ void scatter_kernel(const int* __restrict__ ei, int E, int n)
{
    const int i = blockIdx.x * blockDim.x + threadIdx.x;
    const int tot = E + n;
    if (i >= tot) return;
    int s, d;
    if (i < E) {
        s = ei[i];
        d = ei[E + i];
    } else {
        s = d = i - E;
    }
    if ((unsigned)d < (unsigned)n && (unsigned)s < (unsigned)n) {
        const int pos = atomicAdd(&g_cur[d], 1);
        if ((unsigned)pos < (unsigned)ETOT)
            g_csr[pos] = s;
    }
}

// ---------------------------------------------------------------------------
// GAT aggregation, warp-per-destination (2-pass softmax, chunked gather).
// L1 epilogue writes hr in FRAGMENT ORDER (bf16 hi/lo) for GEMM2's A loads.
// ---------------------------------------------------------------------------
#define AGG_WARPS 8

template <int HEADS, int RP, bool L1>
__global__ void __launch_bounds__(AGG_WARPS * 32)
agg_kernel(const float* __restrict__ bias,
           float* __restrict__ out_ext, int n)
{
    constexpr int D = RP * 32;
    const float* __restrict__ h  = L1 ? g_h1  : g_h2;
    const float* __restrict__ as = L1 ? g_as1 : g_as2;
    const float* __restrict__ ad = L1 ? g_ad1 : g_ad2;

    __shared__ int   s_src[AGG_WARPS][32];
    __shared__ float s_w[AGG_WARPS][32][HEADS];

    const int warp  = (blockIdx.x * blockDim.x + threadIdx.x) >> 5;
    const int wslot = threadIdx.x >> 5;
    const int lane  = threadIdx.x & 31;
    if (warp >= n) return;

    const int start = g_row[warp];
    const int end   = g_row[warp + 1];

    float adv[HEADS];
#pragma unroll
    for (int hh = 0; hh < HEADS; hh++) adv[hh] = ad[warp * HEADS + hh];

    // ---- pass A: sum of exp ----
    float ssum[HEADS];
#pragma unroll
    for (int hh = 0; hh < HEADS; hh++) ssum[hh] = 0.f;
    for (int i = start + lane; i < end; i += 32) {
        const int s = g_csr[i];
#pragma unroll
        for (int hh = 0; hh < HEADS; hh++) {
            float e = as[s * HEADS + hh] + adv[hh];
            e = (e >= 0.f) ? e : NEG_SLOPE * e;
            ssum[hh] += __expf(e);
        }
    }
#pragma unroll
    for (int hh = 0; hh < HEADS; hh++) {
#pragma unroll
        for (int off = 16; off > 0; off >>= 1)
            ssum[hh] += __shfl_xor_sync(0xffffffffu, ssum[hh], off);
    }
    float inv[HEADS];
#pragma unroll
    for (int hh = 0; hh < HEADS; hh++) inv[hh] = 1.0f / ssum[hh];

    // ---- pass B: chunked weighted gather-accumulate ----
    const int head = (lane * RP) >> 6;
    float acc[RP];
#pragma unroll
    for (int r = 0; r < RP; r++) acc[r] = 0.f;

    for (int base = start; base < end; base += 32) {
        const int cnt = min(32, end - base);
        const int i = base + lane;
        if (lane < cnt) {
            const int s = g_csr[i];
            s_src[wslot][lane] = s;
#pragma unroll
            for (int hh = 0; hh < HEADS; hh++) {
                float e = as[s * HEADS + hh] + adv[hh];
                e = (e >= 0.f) ? e : NEG_SLOPE * e;
                s_w[wslot][lane][hh] = __expf(e) * inv[hh];
            }
        }
        __syncwarp();

#pragma unroll 2
        for (int j = 0; j < cnt; j++) {
            const int s   = s_src[wslot][j];
            const float w = s_w[wslot][j][head];
            const float* rowp = h + (size_t)s * D + lane * RP;
            if constexpr (RP == 8) {
                const float4 v0 = *reinterpret_cast<const float4*>(rowp);
                const float4 v1 = *reinterpret_cast<const float4*>(rowp + 4);
                acc[0] += w * v0.x; acc[1] += w * v0.y;
                acc[2] += w * v0.z; acc[3] += w * v0.w;
                acc[4] += w * v1.x; acc[5] += w * v1.y;
                acc[6] += w * v1.z; acc[7] += w * v1.w;
            } else {
                const float2 v0 = *reinterpret_cast<const float2*>(rowp);
                acc[0] += w * v0.x; acc[1] += w * v0.y;
            }
        }
        __syncwarp();
    }

    // ---- epilogue ----
#pragma unroll
    for (int r = 0; r < RP; r++) {
        float v = acc[r] + bias[lane * RP + r];
        if (L1) v = fmaxf(v, 0.f);
        acc[r] = v;
    }
    if constexpr (L1) {
        // bf16 hi/lo split, written in FRAGMENT ORDER for GEMM2
        __nv_bfloat16 hb[RP], lb[RP];
#pragma unroll
        for (int r = 0; r < RP; r++) {
            hb[r] = __float2bfloat16(acc[r]);
            lb[r] = __float2bfloat16(acc[r] - __bfloat162float(hb[r]));
        }
        const int r  = warp;
        const int rb = r >> 4;
        const int kb = lane >> 1;
        const int q  = ((r >> 3) & 1) | ((lane & 1) << 1);
        const size_t fbase = ((size_t)(rb * (D1 / 16) + kb)) * 256
                           + ((r & 7) << 2) * 8 + q * 2;
#pragma unroll
        for (int t = 0; t < 4; t++) {
            *reinterpret_cast<__nv_bfloat162*>(g_hrh + fbase + t * 8) =
                __nv_bfloat162{hb[2 * t], hb[2 * t + 1]};
            *reinterpret_cast<__nv_bfloat162*>(g_hrl + fbase + t * 8) =
                __nv_bfloat162{lb[2 * t], lb[2 * t + 1]};
        }
    } else {
        float* op = out_ext + (size_t)warp * D + lane * RP;
        *reinterpret_cast<float2*>(op) = make_float2(acc[0], acc[1]);
    }
}

// ---------------------------------------------------------------------------
// Launch — kernel launches ONLY.  GEMM1 at captured index 3.
// ---------------------------------------------------------------------------
extern "C" void kernel_launch(void* const* d_in, const int* in_sizes, int n_in,
                              void* d_out, int out_size)
{
    const float* x      = (const float*)d_in[0];
    const int*   ei     = (const int*)d_in[1];   // int32 (JAX x64 disabled)
    const float* W1     = (const float*)d_in[2];
    const float* a_src1 = (const float*)d_in[3];
    const float* a_dst1 = (const float*)d_in[4];
    const float* b1     = (const float*)d_in[5];
    const float* W2     = (const float*)d_in[6];
    const float* a_src2 = (const float*)d_in[7];
    const float* a_dst2 = (const float*)d_in[8];
    const float* b2     = (const float*)d_in[9];
    float*       out    = (float*)d_out;

    const int n = in_sizes[0] / IND;      // 50000
    const int E = in_sizes[1] / 2;        // 800000
    const int tot = E + n;

    const int nb256 = (n + 255) / 256;
    const int eb256 = (tot + 255) / 256;
    const int nscan = (n + 1023) / 1024;

    // 0: fused bf16 splits (x in frag order)
    {
        const int items = n * 32 + IND * D1 / 4 + D1 * D2 / 4;
        split_all_kernel<<<(items + 255) / 256, 256>>>(x, W1, W2, n);
    }
    // 1: zero deg + alpha accumulators
    zero_all_kernel<<<(n * NHEADS + 255) / 256, 256>>>(n);
    // 2: histogram
    hist_kernel<<<eb256, 256>>>(ei, E, n);
    // 3: GEMM1 (+ fused alpha1)  <- ncu captures this index
    {
        dim3 grid(D1 / 64, (n + 127) / 128);
        mma_gemm_kernel<1><<<grid, 256>>>(n, a_src1, a_dst1);
    }
    // 4-7: scan + scatter
    scan1_kernel<<<nscan, 1024>>>(n);
    scan2_kernel<<<1, 64>>>(nscan, n);
    scan3_kernel<<<nb256, 256>>>(n);
    scatter_kernel<<<eb256, 256>>>(ei, E, n);
    // 8: aggregation layer 1 (writes hr in frag order)
    {
        const int grid = (n + AGG_WARPS - 1) / AGG_WARPS;
        agg_kernel<NHEADS, 8, true><<<grid, AGG_WARPS * 32>>>(b1, nullptr, n);
    }
    // 9: GEMM2 (+ fused alpha2)
    {
        dim3 grid(D2 / 64, (n + 127) / 128);
        mma_gemm_kernel<2><<<grid, 256>>>(n, a_src2, a_dst2);
    }
    // 10: aggregation layer 2 -> out
    {
        const int grid = (n + AGG_WARPS - 1) / AGG_WARPS;
        agg_kernel<1, 2, false><<<grid, AGG_WARPS * 32>>>(b2, out, n);
    }
}

// round 12
// speedup vs baseline: 1.1467x; 1.1467x over previous
#include <cuda_runtime.h>
#include <cuda_bf16.h>
#include <cstdint>
#include <cmath>

// Problem constants (match reference_code)
#define NN     50000
#define NNP    50048   // NN padded to multiple of 128 (frag-ordered A arrays)
#define EE     800000
#define ETOT   (NN + EE)
#define IND    256
#define HIDD   64
#define NHEADS 4
#define D1     256
#define D2     64
#define NEG_SLOPE 0.2f

// ---------------------------------------------------------------------------
// Scratch.  g_xh/g_xl/g_hrh/g_hrl are stored in MMA-FRAGMENT ORDER:
//   block (rb, kb) of 16x16; within block: lane = ((r&7)<<2)|((c&7)>>1),
//   q = ((r>>3)&1)|(((c>>3)&1)<<1), elem = c&1;
//   offset = (rb*(K/16)+kb)*256 + lane*8 + q*2 + elem.
// ---------------------------------------------------------------------------
__device__ __align__(16) float g_h1[(size_t)NN * D1];
__device__ __align__(16) float g_h2[(size_t)NN * D2];
__device__ __align__(16) __nv_bfloat16 g_xh[(size_t)NNP * IND];   // frag order
__device__ __align__(16) __nv_bfloat16 g_xl[(size_t)NNP * IND];   // frag order
__device__ __align__(16) __nv_bfloat16 g_w1h[IND * D1];           // flat
__device__ __align__(16) __nv_bfloat16 g_w1l[IND * D1];
__device__ __align__(16) __nv_bfloat16 g_w2h[D1 * D2];
__device__ __align__(16) __nv_bfloat16 g_w2l[D1 * D2];
__device__ __align__(16) __nv_bfloat16 g_hrh[(size_t)NNP * D1];   // frag order
__device__ __align__(16) __nv_bfloat16 g_hrl[(size_t)NNP * D1];   // frag order
__device__ __align__(16) float g_as1[NN * NHEADS];
__device__ __align__(16) float g_ad1[NN * NHEADS];
__device__ __align__(16) float g_as2[NN];
__device__ __align__(16) float g_ad2[NN];
__device__ int   g_deg[NN];
__device__ int   g_row[NN + 1];
__device__ int   g_cur[NN];
__device__ int   g_csr[ETOT];
__device__ int   g_bsum[64];
__device__ int   g_boff[64];

// ---------------------------------------------------------------------------
// PTX helpers
// ---------------------------------------------------------------------------
__device__ __forceinline__ uint32_t sptr(const void* p) {
    return (uint32_t)__cvta_generic_to_shared(p);
}
__device__ __forceinline__ void ldsm4t(uint32_t* r, uint32_t a) {
    asm volatile("ldmatrix.sync.aligned.m8n8.x4.trans.shared.b16 {%0,%1,%2,%3}, [%4];"
                 : "=r"(r[0]), "=r"(r[1]), "=r"(r[2]), "=r"(r[3]) : "r"(a));
}
__device__ __forceinline__ void mma16816(float* c, const uint32_t* a, const uint32_t* b) {
    asm volatile(
        "mma.sync.aligned.m16n8k16.row.col.f32.bf16.bf16.f32 "
        "{%0,%1,%2,%3},{%4,%5,%6,%7},{%8,%9},{%0,%1,%2,%3};"
        : "+f"(c[0]), "+f"(c[1]), "+f"(c[2]), "+f"(c[3])
        : "r"(a[0]), "r"(a[1]), "r"(a[2]), "r"(a[3]), "r"(b[0]), "r"(b[1]));
}
__device__ __forceinline__ __nv_bfloat162 split2(float2 v, __nv_bfloat162* lo) {
    const __nv_bfloat16 h0 = __float2bfloat16(v.x);
    const __nv_bfloat16 h1 = __float2bfloat16(v.y);
    lo->x = __float2bfloat16(v.x - __bfloat162float(h0));
    lo->y = __float2bfloat16(v.y - __bfloat162float(h1));
    return __nv_bfloat162{h0, h1};
}

// ---------------------------------------------------------------------------
// x -> frag-ordered bf16 hi/lo.  One warp per 16x16 frag block; lane computes
// its own 8 frag elements with 4 sectored float2 reads, writes 1 uint4/array.
// ---------------------------------------------------------------------------
__global__ void split_x_kernel(const float* __restrict__ x, int n, int nbw)
{
    const int wb   = (blockIdx.x * blockDim.x + threadIdx.x) >> 5;
    const int lane = threadIdx.x & 31;
    if (wb >= nbw) return;
    const int rb = wb >> 4;          // IND/16 = 16 kb blocks per row-block
    const int kb = wb & 15;
    const int r0 = rb * 16 + (lane >> 2);
    const int r1 = r0 + 8;
    const int c  = kb * 16 + ((lane & 3) << 1);

    const float2 z = make_float2(0.f, 0.f);
    const float2 a0 = (r0 < n) ? *reinterpret_cast<const float2*>(x + (size_t)r0 * IND + c)     : z;
    const float2 a1 = (r0 < n) ? *reinterpret_cast<const float2*>(x + (size_t)r0 * IND + c + 8) : z;
    const float2 b0 = (r1 < n) ? *reinterpret_cast<const float2*>(x + (size_t)r1 * IND + c)     : z;
    const float2 b1 = (r1 < n) ? *reinterpret_cast<const float2*>(x + (size_t)r1 * IND + c + 8) : z;

    __nv_bfloat162 h[4], l[4];
    h[0] = split2(a0, &l[0]);   // q0: r-low,  c-low
    h[1] = split2(b0, &l[1]);   // q1: r-high, c-low
    h[2] = split2(a1, &l[2]);   // q2: r-low,  c-high
    h[3] = split2(b1, &l[3]);   // q3: r-high, c-high

    const size_t off = (size_t)wb * 256 + lane * 8;
    *reinterpret_cast<uint4*>(g_xh + off) = *reinterpret_cast<uint4*>(h);
    *reinterpret_cast<uint4*>(g_xl + off) = *reinterpret_cast<uint4*>(l);
}

// ---------------------------------------------------------------------------
// W1/W2 -> flat bf16 hi/lo (B operands stay smem/ldsm-staged)
// ---------------------------------------------------------------------------
__global__ void split_w_kernel(const float* __restrict__ W1,
                               const float* __restrict__ W2)
{
    constexpr int W1_4 = IND * D1 / 4;
    constexpr int W2_4 = D1 * D2 / 4;
    int j = blockIdx.x * blockDim.x + threadIdx.x;
    const float* src;
    __nv_bfloat16 *hi, *lo;
    if (j < W1_4)             { src = W1; hi = g_w1h; lo = g_w1l; }
    else if (j < W1_4 + W2_4) { j -= W1_4; src = W2; hi = g_w2h; lo = g_w2l; }
    else return;

    const float4 v = reinterpret_cast<const float4*>(src)[j];
    const float vv[4] = {v.x, v.y, v.z, v.w};
    __nv_bfloat16 h[4], l[4];
#pragma unroll
    for (int q = 0; q < 4; q++) {
        h[q] = __float2bfloat16(vv[q]);
        l[q] = __float2bfloat16(vv[q] - __bfloat162float(h[q]));
    }
    reinterpret_cast<__nv_bfloat162*>(hi)[2 * j + 0] = __nv_bfloat162{h[0], h[1]};
    reinterpret_cast<__nv_bfloat162*>(hi)[2 * j + 1] = __nv_bfloat162{h[2], h[3]};
    reinterpret_cast<__nv_bfloat162*>(lo)[2 * j + 0] = __nv_bfloat162{l[0], l[1]};
    reinterpret_cast<__nv_bfloat162*>(lo)[2 * j + 1] = __nv_bfloat162{l[2], l[3]};
}

// ---------------------------------------------------------------------------
// Zero: g_deg + all atomically-accumulated alpha dots
// ---------------------------------------------------------------------------
__global__ void zero_all_kernel(int n)
{
    const int i = blockIdx.x * blockDim.x + threadIdx.x;
    if (i < n) {
        g_deg[i] = 0;
        g_as2[i] = 0.f;
        g_ad2[i] = 0.f;
    }
    if (i < n * NHEADS) {
        g_as1[i] = 0.f;
        g_ad1[i] = 0.f;
    }
}

// ---------------------------------------------------------------------------
// Tensor-core GEMM (bf16 3-term split), 128x64 tile, 2 CTAs/SM.
// A fragments loaded DIRECTLY from frag-ordered global (no smem for A).
// B (weights) staged through smem + ldsm4t.  Fused alpha-dot epilogue.
// ---------------------------------------------------------------------------
template <int LAYER>
__global__ void __launch_bounds__(256, 2)
mma_gemm_kernel(int M, const float* __restrict__ avec_s,
                const float* __restrict__ avec_d)
{
    constexpr int K  = 256;
    constexpr int N  = (LAYER == 1) ? D1 : D2;
    constexpr int BN = 64;
    constexpr int BM = 128;
    constexpr int BK = 32;
    constexpr int NP = BN + 8;
    constexpr int NT = 4;

    const __nv_bfloat16* __restrict__ Ah = (LAYER == 1) ? g_xh  : g_hrh;
    const __nv_bfloat16* __restrict__ Al = (LAYER == 1) ? g_xl  : g_hrl;
    const __nv_bfloat16* __restrict__ Bh = (LAYER == 1) ? g_w1h : g_w2h;
    const __nv_bfloat16* __restrict__ Bl = (LAYER == 1) ? g_w1l : g_w2l;
    float* __restrict__ C                = (LAYER == 1) ? g_h1  : g_h2;
    float* __restrict__ as_out           = (LAYER == 1) ? g_as1 : g_as2;
    float* __restrict__ ad_out           = (LAYER == 1) ? g_ad1 : g_ad2;

    __shared__ __align__(16) __nv_bfloat16 sBh[BK][NP], sBl[BK][NP];

    const int tid  = threadIdx.x;
    const int lane = tid & 31;
    const int wid  = tid >> 5;
    const int wm   = (wid & 3) * 32;
    const int wn   = (wid >> 2) * 32;
    const int brow = blockIdx.y * BM;
    const int bcol = blockIdx.x * BN;

    const int bkr = tid >> 3;
    const int bnc = (tid & 7) * 8;

    uint4 ub_h, ub_l;
    auto gloadB = [&](int k0) {
        const size_t off = (size_t)(k0 + bkr) * N + bcol + bnc;
        ub_h = *reinterpret_cast<const uint4*>(Bh + off);
        ub_l = *reinterpret_cast<const uint4*>(Bl + off);
    };
    auto sstoreB = [&]() {
        *reinterpret_cast<uint4*>(&sBh[bkr][bnc]) = ub_h;
        *reinterpret_cast<uint4*>(&sBl[bkr][bnc]) = ub_l;
    };

    uint4 uah[2][2], ual[2][2];
    auto aload = [&](int kt) {
#pragma unroll
        for (int ks = 0; ks < 2; ks++)
#pragma unroll
            for (int i = 0; i < 2; i++) {
                const int rb = (brow + wm + i * 16) >> 4;
                const int kb = kt * 2 + ks;
                const size_t off = ((size_t)(rb * (K / 16) + kb)) * 256 + lane * 8;
                uah[ks][i] = *reinterpret_cast<const uint4*>(Ah + off);
                ual[ks][i] = *reinterpret_cast<const uint4*>(Al + off);
            }
    };

    float c[2][NT][4];
#pragma unroll
    for (int i = 0; i < 2; i++)
#pragma unroll
        for (int j = 0; j < NT; j++)
#pragma unroll
            for (int q = 0; q < 4; q++) c[i][j][q] = 0.f;

    gloadB(0);
    sstoreB();
    aload(0);
    __syncthreads();

    constexpr int NKT = K / BK;   // 8
    for (int kt = 0; kt < NKT; kt++) {
        if (kt + 1 < NKT) gloadB((kt + 1) * BK);

#pragma unroll
        for (int ks = 0; ks < 2; ks++) {
            const int k16 = ks * 16;
            uint32_t fb_h[NT][2], fb_l[NT][2];
#pragma unroll
            for (int j = 0; j < NT / 2; j++) {
                const int rr = k16 + (lane & 15);
                const int cc = wn + j * 16 + 8 * (lane >> 4);
                uint32_t t[4];
                ldsm4t(t, sptr(&sBh[rr][cc]));
                fb_h[2 * j][0] = t[0]; fb_h[2 * j][1] = t[1];
                fb_h[2 * j + 1][0] = t[2]; fb_h[2 * j + 1][1] = t[3];
                ldsm4t(t, sptr(&sBl[rr][cc]));
                fb_l[2 * j][0] = t[0]; fb_l[2 * j][1] = t[1];
                fb_l[2 * j + 1][0] = t[2]; fb_l[2 * j + 1][1] = t[3];
            }
#pragma unroll
            for (int i = 0; i < 2; i++) {
                const uint32_t* fah = reinterpret_cast<const uint32_t*>(&uah[ks][i]);
                const uint32_t* fal = reinterpret_cast<const uint32_t*>(&ual[ks][i]);
#pragma unroll
                for (int j = 0; j < NT; j++) {
                    mma16816(c[i][j], fah, fb_h[j]);
                    mma16816(c[i][j], fah, fb_l[j]);
                    mma16816(c[i][j], fal, fb_h[j]);
                }
            }
        }

        __syncthreads();
        if (kt + 1 < NKT) {
            sstoreB();
            aload(kt + 1);
            __syncthreads();
        }
    }

    // ---- epilogue: store C + fused (partial) alpha dots ----
    const int head = (LAYER == 1) ? (bcol >> 6) : 0;
#pragma unroll
    for (int i = 0; i < 2; i++) {
        float s0 = 0.f, s1 = 0.f, d0 = 0.f, d1 = 0.f;
#pragma unroll
        for (int j = 0; j < NT; j++) {
            const int col = bcol + wn + j * 8 + (lane & 3) * 2;
            const float a0 = __ldg(avec_s + col), a1 = __ldg(avec_s + col + 1);
            const float b0 = __ldg(avec_d + col), b1 = __ldg(avec_d + col + 1);
            s0 += c[i][j][0] * a0 + c[i][j][1] * a1;
            s1 += c[i][j][2] * a0 + c[i][j][3] * a1;
            d0 += c[i][j][0] * b0 + c[i][j][1] * b1;
            d1 += c[i][j][2] * b0 + c[i][j][3] * b1;

            const int r = brow + wm + i * 16 + (lane >> 2);
            if (r < M)
                *reinterpret_cast<float2*>(C + (size_t)r * N + col) =
                    make_float2(c[i][j][0], c[i][j][1]);
            if (r + 8 < M)
                *reinterpret_cast<float2*>(C + (size_t)(r + 8) * N + col) =
                    make_float2(c[i][j][2], c[i][j][3]);
        }
#pragma unroll
        for (int off = 1; off <= 2; off <<= 1) {
            s0 += __shfl_xor_sync(0xffffffffu, s0, off);
            s1 += __shfl_xor_sync(0xffffffffu, s1, off);
            d0 += __shfl_xor_sync(0xffffffffu, d0, off);
            d1 += __shfl_xor_sync(0xffffffffu, d1, off);
        }
        if ((lane & 3) == 0) {
            const int r = brow + wm + i * 16 + (lane >> 2);
            const int stride = (LAYER == 1) ? NHEADS : 1;
            if (r < M) {
                atomicAdd(&as_out[r * stride + head], s0);
                atomicAdd(&ad_out[r * stride + head], d0);
            }
            if (r + 8 < M) {
                atomicAdd(&as_out[(r + 8) * stride + head], s1);
                atomicAdd(&ad_out[(r + 8) * stride + head], d1);
            }
        }
    }
}

// ---------------------------------------------------------------------------
// CSR build
// ---------------------------------------------------------------------------
__global__ void hist_kernel(const int* __restrict__ ei, int E, int n)
{
    const int i = blockIdx.x * blockDim.x + threadIdx.x;
    const int tot = E + n;
    if (i >= tot) return;
    const int d = (i < E) ? ei[E + i] : (i - E);
    if ((unsigned)d < (unsigned)n)
        atomicAdd(&g_deg[d], 1);
}

__global__ void scan1_kernel(int n)
{
    __shared__ int smem[1024];
    const int tid = threadIdx.x;
    const int i = blockIdx.x * 1024 + tid;
    const int v = (i < n) ? g_deg[i] : 0;
    int x = v;
#pragma unroll
    for (int off = 1; off < 1024; off <<= 1) {
        smem[tid] = x;
        __syncthreads();
        if (tid >= off) x += smem[tid - off];
        __syncthreads();
    }
    if (i < n) g_row[i] = x - v;
    if (tid == 1023) g_bsum[blockIdx.x] = x;
}

__global__ void scan2_kernel(int nb, int n)
{
    __shared__ int sm[64];
    const int tid = threadIdx.x;
    const int v = (tid < nb) ? g_bsum[tid] : 0;
    int x = v;
#pragma unroll
    for (int off = 1; off < 64; off <<= 1) {
        sm[tid] = x;
        __syncthreads();
        if (tid >= off) x += sm[tid - off];
        __syncthreads();
    }
    if (tid < nb) g_boff[tid] = x - v;
    if (tid == 63) g_row[n] = x;
}

__global__ void scan3_kernel(int n)
{
    const int i = blockIdx.x * blockDim.x + threadIdx.x;
    if (i >= n) return;
    const int v = g_row[i] + g_boff[i >> 10];
    g_row[i] = v;
    g_cur[i] = v;
}

__global__ void scatter_kernel(const int* __restrict__ ei, int E, int n)
{
    const int i = blockIdx.x * blockDim.x + threadIdx.x;
    const int tot = E + n;
    if (i >= tot) return;
    int s, d;
    if (i < E) {
        s = ei[i];
        d = ei[E + i];
    } else {
        s = d = i - E;
    }
    if ((unsigned)d < (unsigned)n && (unsigned)s < (unsigned)n) {
        const int pos = atomicAdd(&g_cur[d], 1);
        if ((unsigned)pos < (unsigned)ETOT)
            g_csr[pos] = s;
    }
}

// ---------------------------------------------------------------------------
// GAT aggregation, warp-per-destination (2-pass softmax, chunked gather).
// L1: NW=16 warps/block = 16 rows = one frag row-block; epilogue stages the
//     bf16 hi/lo split in smem (padded, 2-way-conflict scatter) and then
//     streams it out as coalesced uint4 stores in frag order.
// L2: NW=8, flat fp32 output to d_out.
// ---------------------------------------------------------------------------
template <int HEADS, int RP, bool L1, int NW>
__global__ void __launch_bounds__(NW * 32)
agg_kernel(const float* __restrict__ bias,
           float* __restrict__ out_ext, int n)
{
    constexpr int D = RP * 32;
    const float* __restrict__ h  = L1 ? g_h1  : g_h2;
    const float* __restrict__ as = L1 ? g_as1 : g_as2;
    const float* __restrict__ ad = L1 ? g_ad1 : g_ad2;

    __shared__ int   s_src[NW][32];
    __shared__ float s_w[NW][32][HEADS];
    // staging for frag-order output (L1 only); 264 = 256 + 8 pad per kb block
    __shared__ __align__(16) __nv_bfloat16 st_h[L1 ? 16 * 264 : 1];
    __shared__ __align__(16) __nv_bfloat16 st_l[L1 ? 16 * 264 : 1];

    const int wslot = threadIdx.x >> 5;
    const int lane  = threadIdx.x & 31;
    const int warp  = blockIdx.x * NW + wslot;
    const bool valid = warp < n;
    if (!L1 && !valid) return;

    int start = 0, end = 0;
    if (valid) {
        start = g_row[warp];
        end   = g_row[warp + 1];
    }

    float adv[HEADS];
#pragma unroll
    for (int hh = 0; hh < HEADS; hh++)
        adv[hh] = valid ? ad[warp * HEADS + hh] : 0.f;

    // ---- pass A: sum of exp ----
    float ssum[HEADS];
#pragma unroll
    for (int hh = 0; hh < HEADS; hh++) ssum[hh] = 0.f;
    for (int i = start + lane; i < end; i += 32) {
        const int s = g_csr[i];
#pragma unroll
        for (int hh = 0; hh < HEADS; hh++) {
            float e = as[s * HEADS + hh] + adv[hh];
            e = (e >= 0.f) ? e : NEG_SLOPE * e;
            ssum[hh] += __expf(e);
        }
    }
#pragma unroll
    for (int hh = 0; hh < HEADS; hh++) {
#pragma unroll
        for (int off = 16; off > 0; off >>= 1)
            ssum[hh] += __shfl_xor_sync(0xffffffffu, ssum[hh], off);
    }
    float inv[HEADS];
#pragma unroll
    for (int hh = 0; hh < HEADS; hh++) inv[hh] = 1.0f / ssum[hh];

    // ---- pass B: chunked weighted gather-accumulate ----
    const int head = (lane * RP) >> 6;
    float acc[RP];
#pragma unroll
    for (int r = 0; r < RP; r++) acc[r] = 0.f;

    for (int base = start; base < end; base += 32) {
        const int cnt = min(32, end - base);
        const int i = base + lane;
        if (lane < cnt) {
            const int s = g_csr[i];
            s_src[wslot][lane] = s;
#pragma unroll
            for (int hh = 0; hh < HEADS; hh++) {
                float e = as[s * HEADS + hh] + adv[hh];
                e = (e >= 0.f) ? e : NEG_SLOPE * e;
                s_w[wslot][lane][hh] = __expf(e) * inv[hh];
            }
        }
        __syncwarp();

#pragma unroll 2
        for (int j = 0; j < cnt; j++) {
            const int s   = s_src[wslot][j];
            const float w = s_w[wslot][j][head];
            const float* rowp = h + (size_t)s * D + lane * RP;
            if constexpr (RP == 8) {
                const float4 v0 = *reinterpret_cast<const float4*>(rowp);
                const float4 v1 = *reinterpret_cast<const float4*>(rowp + 4);
                acc[0] += w * v0.x; acc[1] += w * v0.y;
                acc[2] += w * v0.z; acc[3] += w * v0.w;
                acc[4] += w * v1.x; acc[5] += w * v1.y;
                acc[6] += w * v1.z; acc[7] += w * v1.w;
            } else {
                const float2 v0 = *reinterpret_cast<const float2*>(rowp);
                acc[0] += w * v0.x; acc[1] += w * v0.y;
            }
        }
        __syncwarp();
    }

    // ---- epilogue ----
#pragma unroll
    for (int r = 0; r < RP; r++) {
        float v = acc[r] + bias[lane * RP + r];
        if (L1) v = fmaxf(v, 0.f);
        acc[r] = v;
    }
    if constexpr (L1) {
        if (valid) {
            // scatter bf16 hi/lo into smem staging (frag order, padded stride)
            const int lr = wslot;                 // local row 0..15
            const int kb = lane >> 1;             // cols lane*8.. -> kb block
            const int q  = ((lr >> 3) & 1) | ((lane & 1) << 1);
#pragma unroll
            for (int t = 0; t < 4; t++) {
                const float v0 = acc[2 * t], v1 = acc[2 * t + 1];
                __nv_bfloat162 lo2;
                const __nv_bfloat162 hi2 = split2(make_float2(v0, v1), &lo2);
                const int o = kb * 264 + (((lr & 7) << 2) + t) * 8 + q * 2;
                *reinterpret_cast<__nv_bfloat162*>(st_h + o) = hi2;
                *reinterpret_cast<__nv_bfloat162*>(st_l + o) = lo2;
            }
        }
        __syncthreads();
        // stream out coalesced: 512 threads x 16B per array
        const int t = threadIdx.x;                // 0..511
        const int kb = t >> 5, inner = t & 31;
        const uint4 vh = *reinterpret_cast<const uint4*>(st_h + kb * 264 + inner * 8);
        const uint4 vl = *reinterpret_cast<const uint4*>(st_l + kb * 264 + inner * 8);
        const size_t off = ((size_t)(blockIdx.x * 16 + kb)) * 256 + inner * 8;
        *reinterpret_cast<uint4*>(g_hrh + off) = vh;
        *reinterpret_cast<uint4*>(g_hrl + off) = vl;
    } else {
        float* op = out_ext + (size_t)warp * D + lane * RP;
        *reinterpret_cast<float2*>(op) = make_float2(acc[0], acc[1]);
    }
}

// ---------------------------------------------------------------------------
// Launch — kernel launches ONLY.  GEMM1 at captured index 3.
// ---------------------------------------------------------------------------
extern "C" void kernel_launch(void* const* d_in, const int* in_sizes, int n_in,
                              void* d_out, int out_size)
{
    const float* x      = (const float*)d_in[0];
    const int*   ei     = (const int*)d_in[1];   // int32 (JAX x64 disabled)
    const float* W1     = (const float*)d_in[2];
    const float* a_src1 = (const float*)d_in[3];
    const float* a_dst1 = (const float*)d_in[4];
    const float* b1     = (const float*)d_in[5];
    const float* W2     = (const float*)d_in[6];
    const float* a_src2 = (const float*)d_in[7];
    const float* a_dst2 = (const float*)d_in[8];
    const float* b2     = (const float*)d_in[9];
    float*       out    = (float*)d_out;

    const int n = in_sizes[0] / IND;      // 50000
    const int E = in_sizes[1] / 2;        // 800000
    const int tot = E + n;

    const int nb256 = (n + 255) / 256;
    const int eb256 = (tot + 255) / 256;
    const int nscan = (n + 1023) / 1024;

    // 0: x -> frag-order bf16 hi/lo (one warp per 16x16 block)
    {
        const int np128 = ((n + 127) / 128) * 128;     // 50048
        const int nbw = (np128 / 16) * (IND / 16);     // frag blocks
        split_x_kernel<<<(nbw + 7) / 8, 256>>>(x, n, nbw);
    }
    // 1: W splits (flat)
    {
        const int items = IND * D1 / 4 + D1 * D2 / 4;
        split_w_kernel<<<(items + 255) / 256, 256>>>(W1, W2);
    }
    // 2: zero deg + alpha accumulators
    zero_all_kernel<<<(n * NHEADS + 255) / 256, 256>>>(n);
    // 3: GEMM1 (+ fused alpha1)  <- ncu captures this index
    {
        dim3 grid(D1 / 64, (n + 127) / 128);
        mma_gemm_kernel<1><<<grid, 256>>>(n, a_src1, a_dst1);
    }
    // 4-8: histogram + scan + scatter
    hist_kernel<<<eb256, 256>>>(ei, E, n);
    scan1_kernel<<<nscan, 1024>>>(n);
    scan2_kernel<<<1, 64>>>(nscan, n);
    scan3_kernel<<<nb256, 256>>>(n);
    scatter_kernel<<<eb256, 256>>>(ei, E, n);
    // 9: aggregation layer 1 (16 warps/block, staged frag-order hr output)
    {
        const int grid = (n + 15) / 16;
        agg_kernel<NHEADS, 8, true, 16><<<grid, 16 * 32>>>(b1, nullptr, n);
    }
    // 10: GEMM2 (+ fused alpha2)
    {
        dim3 grid(D2 / 64, (n + 127) / 128);
        mma_gemm_kernel<2><<<grid, 256>>>(n, a_src2, a_dst2);
    }
    // 11: aggregation layer 2 -> out
    {
        const int grid = (n + 7) / 8;
        agg_kernel<1, 2, false, 8><<<grid, 8 * 32>>>(b2, out, n);
    }
}

// round 13
// speedup vs baseline: 1.2563x; 1.0956x over previous
#include <cuda_runtime.h>
#include <cuda_bf16.h>
#include <cstdint>
#include <cmath>

// Problem constants (match reference_code)
#define NN     50000
#define NNP    50048   // NN padded to multiple of 128 (frag-ordered A arrays)
#define EE     800000
#define ETOT   (NN + EE)
#define IND    256
#define HIDD   64
#define NHEADS 4
#define D1     256
#define D2     64
#define NEG_SLOPE 0.2f

// ---------------------------------------------------------------------------
// Scratch.  A-side arrays (g_xh/g_xl/g_hrh/g_hrl) in MMA A-FRAGMENT ORDER:
//   16x16 block (rb,kb): offset = (rb*(K/16)+kb)*256 + lane*8 + q*2 + e
//   lane = ((r&7)<<2)|((c&7)>>1), q = ((r>>3)&1)|(((c>>3)&1)<<1), e = c&1.
// W arrays in MMA B-FRAGMENT ORDER:
//   8x16 block (nb8,kbb): offset = (nb8*(K/16)+kbb)*128 + lane*4 + reg*2 + e
//   n = nb8*8 + (lane>>2), k = kbb*16 + (lane&3)*2 + reg*8 + e.
// ---------------------------------------------------------------------------
__device__ __align__(16) float g_h1[(size_t)NN * D1];
__device__ __align__(16) float g_h2[(size_t)NN * D2];
__device__ __align__(16) __nv_bfloat16 g_xh[(size_t)NNP * IND];
__device__ __align__(16) __nv_bfloat16 g_xl[(size_t)NNP * IND];
__device__ __align__(16) __nv_bfloat16 g_w1h[IND * D1];
__device__ __align__(16) __nv_bfloat16 g_w1l[IND * D1];
__device__ __align__(16) __nv_bfloat16 g_w2h[D1 * D2];
__device__ __align__(16) __nv_bfloat16 g_w2l[D1 * D2];
__device__ __align__(16) __nv_bfloat16 g_hrh[(size_t)NNP * D1];
__device__ __align__(16) __nv_bfloat16 g_hrl[(size_t)NNP * D1];
__device__ __align__(16) float g_as1[NN * NHEADS];
__device__ __align__(16) float g_ad1[NN * NHEADS];
__device__ __align__(16) float g_as2[NN];
__device__ __align__(16) float g_ad2[NN];
__device__ int   g_deg[NN];
__device__ int   g_row[NN + 1];
__device__ int   g_cur[NN];
__device__ int   g_csr[ETOT];
__device__ int   g_bsum[64];
__device__ int   g_boff[64];

// ---------------------------------------------------------------------------
// helpers
// ---------------------------------------------------------------------------
__device__ __forceinline__ void mma16816(float* c, const uint32_t* a, const uint32_t* b) {
    asm volatile(
        "mma.sync.aligned.m16n8k16.row.col.f32.bf16.bf16.f32 "
        "{%0,%1,%2,%3},{%4,%5,%6,%7},{%8,%9},{%0,%1,%2,%3};"
        : "+f"(c[0]), "+f"(c[1]), "+f"(c[2]), "+f"(c[3])
        : "r"(a[0]), "r"(a[1]), "r"(a[2]), "r"(a[3]), "r"(b[0]), "r"(b[1]));
}
__device__ __forceinline__ __nv_bfloat162 split2(float2 v, __nv_bfloat162* lo) {
    const __nv_bfloat16 h0 = __float2bfloat16(v.x);
    const __nv_bfloat16 h1 = __float2bfloat16(v.y);
    lo->x = __float2bfloat16(v.x - __bfloat162float(h0));
    lo->y = __float2bfloat16(v.y - __bfloat162float(h1));
    return __nv_bfloat162{h0, h1};
}
__device__ __forceinline__ uint32_t b2u(__nv_bfloat162 v) {
    return *reinterpret_cast<uint32_t*>(&v);
}

// ---------------------------------------------------------------------------
// prep: x -> A-frag bf16 hi/lo, W1/W2 -> B-frag bf16 hi/lo, zero accumulators.
// One launch; dispatch on blockIdx range.
// ---------------------------------------------------------------------------
__global__ void prep_kernel(const float* __restrict__ x,
                            const float* __restrict__ W1,
                            const float* __restrict__ W2,
                            int n, int xwb)
{
    const int xblocks = (xwb + 7) >> 3;
    const int bid = blockIdx.x;
    const int lane = threadIdx.x & 31;

    if (bid < xblocks) {
        // ---- x split: one warp per 16x16 A-frag block ----
        const int wb = bid * 8 + (threadIdx.x >> 5);
        if (wb >= xwb) return;
        const int rb = wb >> 4;
        const int kb = wb & 15;
        const int r0 = rb * 16 + (lane >> 2);
        const int r1 = r0 + 8;
        const int c  = kb * 16 + ((lane & 3) << 1);

        const float2 z = make_float2(0.f, 0.f);
        const float2 a0 = (r0 < n) ? *reinterpret_cast<const float2*>(x + (size_t)r0 * IND + c)     : z;
        const float2 a1 = (r0 < n) ? *reinterpret_cast<const float2*>(x + (size_t)r0 * IND + c + 8) : z;
        const float2 b0 = (r1 < n) ? *reinterpret_cast<const float2*>(x + (size_t)r1 * IND + c)     : z;
        const float2 b1 = (r1 < n) ? *reinterpret_cast<const float2*>(x + (size_t)r1 * IND + c + 8) : z;

        __nv_bfloat162 h[4], l[4];
        h[0] = split2(a0, &l[0]);
        h[1] = split2(b0, &l[1]);
        h[2] = split2(a1, &l[2]);
        h[3] = split2(b1, &l[3]);

        const size_t off = (size_t)wb * 256 + lane * 8;
        *reinterpret_cast<uint4*>(g_xh + off) = *reinterpret_cast<uint4*>(h);
        *reinterpret_cast<uint4*>(g_xl + off) = *reinterpret_cast<uint4*>(l);
        return;
    }

    int b2 = bid - xblocks;
    if (b2 < 80) {
        // ---- W split: one warp per 8x16 B-frag block ----
        const int widx = b2 * 8 + (threadIdx.x >> 5);   // 0..639
        if (widx >= 640) return;
        const float* W;
        __nv_bfloat16 *dh, *dl;
        int Nn, blkid;
        if (widx < 512) { W = W1; dh = g_w1h; dl = g_w1l; Nn = D1; blkid = widx; }
        else            { W = W2; dh = g_w2h; dl = g_w2l; Nn = D2; blkid = widx - 512; }
        const int nb8 = blkid >> 4, kbb = blkid & 15;
        const int nn = nb8 * 8 + (lane >> 2);
        const int k0 = kbb * 16 + (lane & 3) * 2;
        const float w00 = W[(size_t)k0 * Nn + nn];
        const float w01 = W[(size_t)(k0 + 1) * Nn + nn];
        const float w10 = W[(size_t)(k0 + 8) * Nn + nn];
        const float w11 = W[(size_t)(k0 + 9) * Nn + nn];
        __nv_bfloat162 l0, l1;
        const __nv_bfloat162 h0 = split2(make_float2(w00, w01), &l0);
        const __nv_bfloat162 h1 = split2(make_float2(w10, w11), &l1);
        *reinterpret_cast<uint2*>(dh + (size_t)blkid * 128 + lane * 4) = make_uint2(b2u(h0), b2u(h1));
        *reinterpret_cast<uint2*>(dl + (size_t)blkid * 128 + lane * 4) = make_uint2(b2u(l0), b2u(l1));
        return;
    }

    // ---- zero ----
    const int i = (b2 - 80) * 256 + threadIdx.x;
    if (i < n) {
        g_deg[i] = 0;
        g_as2[i] = 0.f;
        g_ad2[i] = 0.f;
    }
    if (i < n * NHEADS) {
        g_as1[i] = 0.f;
        g_ad1[i] = 0.f;
    }
}

// ---------------------------------------------------------------------------
// Tensor-core GEMM (bf16 3-term split), NO shared memory, no barriers.
// A and B fragments loaded directly from frag-ordered global.
// 128x64 CTA tile, 8 warps (4m x 2n), warp tile 32x32, 2 CTAs/SM.
// Fused alpha-dot epilogue (atomicAdd partials).
// ---------------------------------------------------------------------------
template <int LAYER>
__global__ void __launch_bounds__(256, 2)
mma_gemm_kernel(int M, const float* __restrict__ avec_s,
                const float* __restrict__ avec_d)
{
    constexpr int K  = 256;
    constexpr int N  = (LAYER == 1) ? D1 : D2;
    constexpr int NT = 4;

    const __nv_bfloat16* __restrict__ Ah = (LAYER == 1) ? g_xh  : g_hrh;
    const __nv_bfloat16* __restrict__ Al = (LAYER == 1) ? g_xl  : g_hrl;
    const __nv_bfloat16* __restrict__ Bh = (LAYER == 1) ? g_w1h : g_w2h;
    const __nv_bfloat16* __restrict__ Bl = (LAYER == 1) ? g_w1l : g_w2l;
    float* __restrict__ C                = (LAYER == 1) ? g_h1  : g_h2;
    float* __restrict__ as_out           = (LAYER == 1) ? g_as1 : g_as2;
    float* __restrict__ ad_out           = (LAYER == 1) ? g_ad1 : g_ad2;

    const int tid  = threadIdx.x;
    const int lane = tid & 31;
    const int wid  = tid >> 5;
    const int wm   = (wid & 3) * 32;
    const int wn   = (wid >> 2) * 32;
    const int brow = blockIdx.y * 128;
    const int bcol = blockIdx.x * 64;

    // A pointers (frag order): +kb*256 per 16-k block
    const __nv_bfloat16* aph[2];
    const __nv_bfloat16* apl[2];
#pragma unroll
    for (int i = 0; i < 2; i++) {
        const int rb = (brow + wm + i * 16) >> 4;
        aph[i] = Ah + (size_t)rb * (K / 16) * 256 + lane * 8;
        apl[i] = Al + (size_t)rb * (K / 16) * 256 + lane * 8;
    }
    // B pointers (frag order): +j*(K/16)*128 per n8 block, +kbb*128 per k16
    const int nb8base = (bcol + wn) >> 3;
    const __nv_bfloat16* bph = Bh + (size_t)nb8base * (K / 16) * 128 + lane * 4;
    const __nv_bfloat16* bpl = Bl + (size_t)nb8base * (K / 16) * 128 + lane * 4;

    uint4 abh[2][2][2], abl[2][2][2];   // [buf][ks][i]
    auto aload = [&](int kt, int buf) {
#pragma unroll
        for (int ks = 0; ks < 2; ks++) {
            const int kb = kt * 2 + ks;
#pragma unroll
            for (int i = 0; i < 2; i++) {
                abh[buf][ks][i] = *reinterpret_cast<const uint4*>(aph[i] + kb * 256);
                abl[buf][ks][i] = *reinterpret_cast<const uint4*>(apl[i] + kb * 256);
            }
        }
    };

    float c[2][NT][4];
#pragma unroll
    for (int i = 0; i < 2; i++)
#pragma unroll
        for (int j = 0; j < NT; j++)
#pragma unroll
            for (int q = 0; q < 4; q++) c[i][j][q] = 0.f;

    aload(0, 0);

#pragma unroll
    for (int kt = 0; kt < K / 32; kt++) {
        if (kt + 1 < K / 32) aload(kt + 1, (kt + 1) & 1);
        const int bf = kt & 1;
#pragma unroll
        for (int ks = 0; ks < 2; ks++) {
            const int kbb = kt * 2 + ks;
            uint2 fbh[NT], fbl[NT];
#pragma unroll
            for (int j = 0; j < NT; j++) {
                fbh[j] = *reinterpret_cast<const uint2*>(bph + j * (K / 16) * 128 + kbb * 128);
                fbl[j] = *reinterpret_cast<const uint2*>(bpl + j * (K / 16) * 128 + kbb * 128);
            }
#pragma unroll
            for (int i = 0; i < 2; i++) {
                const uint32_t* fah = reinterpret_cast<const uint32_t*>(&abh[bf][ks][i]);
                const uint32_t* fal = reinterpret_cast<const uint32_t*>(&abl[bf][ks][i]);
#pragma unroll
                for (int j = 0; j < NT; j++) {
                    mma16816(c[i][j], fah, reinterpret_cast<const uint32_t*>(&fbh[j]));
                    mma16816(c[i][j], fah, reinterpret_cast<const uint32_t*>(&fbl[j]));
                    mma16816(c[i][j], fal, reinterpret_cast<const uint32_t*>(&fbh[j]));
                }
            }
        }
    }

    // ---- epilogue: store C + fused (partial) alpha dots ----
    const int head = (LAYER == 1) ? (bcol >> 6) : 0;
#pragma unroll
    for (int i = 0; i < 2; i++) {
        float s0 = 0.f, s1 = 0.f, d0 = 0.f, d1 = 0.f;
#pragma unroll
        for (int j = 0; j < NT; j++) {
            const int col = bcol + wn + j * 8 + (lane & 3) * 2;
            const float a0 = __ldg(avec_s + col), a1 = __ldg(avec_s + col + 1);
            const float b0 = __ldg(avec_d + col), b1 = __ldg(avec_d + col + 1);
            s0 += c[i][j][0] * a0 + c[i][j][1] * a1;
            s1 += c[i][j][2] * a0 + c[i][j][3] * a1;
            d0 += c[i][j][0] * b0 + c[i][j][1] * b1;
            d1 += c[i][j][2] * b0 + c[i][j][3] * b1;

            const int r = brow + wm + i * 16 + (lane >> 2);
            if (r < M)
                *reinterpret_cast<float2*>(C + (size_t)r * N + col) =
                    make_float2(c[i][j][0], c[i][j][1]);
            if (r + 8 < M)
                *reinterpret_cast<float2*>(C + (size_t)(r + 8) * N + col) =
                    make_float2(c[i][j][2], c[i][j][3]);
        }
#pragma unroll
        for (int off = 1; off <= 2; off <<= 1) {
            s0 += __shfl_xor_sync(0xffffffffu, s0, off);
            s1 += __shfl_xor_sync(0xffffffffu, s1, off);
            d0 += __shfl_xor_sync(0xffffffffu, d0, off);
            d1 += __shfl_xor_sync(0xffffffffu, d1, off);
        }
        if ((lane & 3) == 0) {
            const int r = brow + wm + i * 16 + (lane >> 2);
            const int stride = (LAYER == 1) ? NHEADS : 1;
            if (r < M) {
                atomicAdd(&as_out[r * stride + head], s0);
                atomicAdd(&ad_out[r * stride + head], d0);
            }
            if (r + 8 < M) {
                atomicAdd(&as_out[(r + 8) * stride + head], s1);
                atomicAdd(&ad_out[(r + 8) * stride + head], d1);
            }
        }
    }
}

// ---------------------------------------------------------------------------
// CSR build
// ---------------------------------------------------------------------------
__global__ void hist_kernel(const int* __restrict__ ei, int E, int n)
{
    const int i = blockIdx.x * blockDim.x + threadIdx.x;
    const int tot = E + n;
    if (i >= tot) return;
    const int d = (i < E) ? ei[E + i] : (i - E);
    if ((unsigned)d < (unsigned)n)
        atomicAdd(&g_deg[d], 1);
}

__global__ void scan1_kernel(int n)
{
    __shared__ int smem[1024];
    const int tid = threadIdx.x;
    const int i = blockIdx.x * 1024 + tid;
    const int v = (i < n) ? g_deg[i] : 0;
    int x = v;
#pragma unroll
    for (int off = 1; off < 1024; off <<= 1) {
        smem[tid] = x;
        __syncthreads();
        if (tid >= off) x += smem[tid - off];
        __syncthreads();
    }
    if (i < n) g_row[i] = x - v;
    if (tid == 1023) g_bsum[blockIdx.x] = x;
}

__global__ void scan2_kernel(int nb, int n)
{
    __shared__ int sm[64];
    const int tid = threadIdx.x;
    const int v = (tid < nb) ? g_bsum[tid] : 0;
    int x = v;
#pragma unroll
    for (int off = 1; off < 64; off <<= 1) {
        sm[tid] = x;
        __syncthreads();
        if (tid >= off) x += sm[tid - off];
        __syncthreads();
    }
    if (tid < nb) g_boff[tid] = x - v;
    if (tid == 63) g_row[n] = x;
}

__global__ void scan3_kernel(int n)
{
    const int i = blockIdx.x * blockDim.x + threadIdx.x;
    if (i >= n) return;
    const int v = g_row[i] + g_boff[i >> 10];
    g_row[i] = v;
    g_cur[i] = v;
}

__global__ void scatter_kernel(const int* __restrict__ ei, int E, int n)
{
    const int i = blockIdx.x * blockDim.x + threadIdx.x;
    const int tot = E + n;
    if (i >= tot) return;
    int s, d;
    if (i < E) {
        s = ei[i];
        d = ei[E + i];
    } else {
        s = d = i - E;
    }
    if ((unsigned)d < (unsigned)n && (unsigned)s < (unsigned)n) {
        const int pos = atomicAdd(&g_cur[d], 1);
        if ((unsigned)pos < (unsigned)ETOT)
            g_csr[pos] = s;
    }
}

// ---------------------------------------------------------------------------
// GAT aggregation, warp-per-destination (2-pass softmax, chunked gather).
// L1: NW=16 rows/block; epilogue stages bf16 hi/lo in smem (A-frag order)
//     then streams coalesced uint4 stores.  L2: NW=8, fp32 out.
// ---------------------------------------------------------------------------
template <int HEADS, int RP, bool L1, int NW>
__global__ void __launch_bounds__(NW * 32)
agg_kernel(const float* __restrict__ bias,
           float* __restrict__ out_ext, int n)
{
    constexpr int D = RP * 32;
    const float* __restrict__ h  = L1 ? g_h1  : g_h2;
    const float* __restrict__ as = L1 ? g_as1 : g_as2;
    const float* __restrict__ ad = L1 ? g_ad1 : g_ad2;

    __shared__ int   s_src[NW][32];
    __shared__ float s_w[NW][32][HEADS];
    __shared__ __align__(16) __nv_bfloat16 st_h[L1 ? 16 * 264 : 1];
    __shared__ __align__(16) __nv_bfloat16 st_l[L1 ? 16 * 264 : 1];

    const int wslot = threadIdx.x >> 5;
    const int lane  = threadIdx.x & 31;
    const int warp  = blockIdx.x * NW + wslot;
    const bool valid = warp < n;
    if (!L1 && !valid) return;

    int start = 0, end = 0;
    if (valid) {
        start = g_row[warp];
        end   = g_row[warp + 1];
    }

    float adv[HEADS];
#pragma unroll
    for (int hh = 0; hh < HEADS; hh++)
        adv[hh] = valid ? ad[warp * HEADS + hh] : 0.f;

    // ---- pass A: sum of exp ----
    float ssum[HEADS];
#pragma unroll
    for (int hh = 0; hh < HEADS; hh++) ssum[hh] = 0.f;
    for (int i = start + lane; i < end; i += 32) {
        const int s = g_csr[i];
#pragma unroll
        for (int hh = 0; hh < HEADS; hh++) {
            float e = as[s * HEADS + hh] + adv[hh];
            e = (e >= 0.f) ? e : NEG_SLOPE * e;
            ssum[hh] += __expf(e);
        }
    }
#pragma unroll
    for (int hh = 0; hh < HEADS; hh++) {
#pragma unroll
        for (int off = 16; off > 0; off >>= 1)
            ssum[hh] += __shfl_xor_sync(0xffffffffu, ssum[hh], off);
    }
    float inv[HEADS];
#pragma unroll
    for (int hh = 0; hh < HEADS; hh++) inv[hh] = 1.0f / ssum[hh];

    // ---- pass B: chunked weighted gather-accumulate ----
    const int head = (lane * RP) >> 6;
    float acc[RP];
#pragma unroll
    for (int r = 0; r < RP; r++) acc[r] = 0.f;

    for (int base = start; base < end; base += 32) {
        const int cnt = min(32, end - base);
        const int i = base + lane;
        if (lane < cnt) {
            const int s = g_csr[i];
            s_src[wslot][lane] = s;
#pragma unroll
            for (int hh = 0; hh < HEADS; hh++) {
                float e = as[s * HEADS + hh] + adv[hh];
                e = (e >= 0.f) ? e : NEG_SLOPE * e;
                s_w[wslot][lane][hh] = __expf(e) * inv[hh];
            }
        }
        __syncwarp();

#pragma unroll 2
        for (int j = 0; j < cnt; j++) {
            const int s   = s_src[wslot][j];
            const float w = s_w[wslot][j][head];
            const float* rowp = h + (size_t)s * D + lane * RP;
            if constexpr (RP == 8) {
                const float4 v0 = *reinterpret_cast<const float4*>(rowp);
                const float4 v1 = *reinterpret_cast<const float4*>(rowp + 4);
                acc[0] += w * v0.x; acc[1] += w * v0.y;
                acc[2] += w * v0.z; acc[3] += w * v0.w;
                acc[4] += w * v1.x; acc[5] += w * v1.y;
                acc[6] += w * v1.z; acc[7] += w * v1.w;
            } else {
                const float2 v0 = *reinterpret_cast<const float2*>(rowp);
                acc[0] += w * v0.x; acc[1] += w * v0.y;
            }
        }
        __syncwarp();
    }

    // ---- epilogue ----
#pragma unroll
    for (int r = 0; r < RP; r++) {
        float v = acc[r] + bias[lane * RP + r];
        if (L1) v = fmaxf(v, 0.f);
        acc[r] = v;
    }
    if constexpr (L1) {
        if (valid) {
            const int lr = wslot;
            const int kb = lane >> 1;
            const int q  = ((lr >> 3) & 1) | ((lane & 1) << 1);
#pragma unroll
            for (int t = 0; t < 4; t++) {
                __nv_bfloat162 lo2;
                const __nv_bfloat162 hi2 = split2(make_float2(acc[2 * t], acc[2 * t + 1]), &lo2);
                const int o = kb * 264 + (((lr & 7) << 2) + t) * 8 + q * 2;
                *reinterpret_cast<__nv_bfloat162*>(st_h + o) = hi2;
                *reinterpret_cast<__nv_bfloat162*>(st_l + o) = lo2;
            }
        }
        __syncthreads();
        const int t = threadIdx.x;
        const int kb = t >> 5, inner = t & 31;
        const uint4 vh = *reinterpret_cast<const uint4*>(st_h + kb * 264 + inner * 8);
        const uint4 vl = *reinterpret_cast<const uint4*>(st_l + kb * 264 + inner * 8);
        const size_t off = ((size_t)(blockIdx.x * 16 + kb)) * 256 + inner * 8;
        *reinterpret_cast<uint4*>(g_hrh + off) = vh;
        *reinterpret_cast<uint4*>(g_hrl + off) = vl;
    } else {
        float* op = out_ext + (size_t)warp * D + lane * RP;
        *reinterpret_cast<float2*>(op) = make_float2(acc[0], acc[1]);
    }
}

// ---------------------------------------------------------------------------
// Launch — kernel launches ONLY.  GEMM1 at captured index 3.
// ---------------------------------------------------------------------------
extern "C" void kernel_launch(void* const* d_in, const int* in_sizes, int n_in,
                              void* d_out, int out_size)
{
    const float* x      = (const float*)d_in[0];
    const int*   ei     = (const int*)d_in[1];   // int32 (JAX x64 disabled)
    const float* W1     = (const float*)d_in[2];
    const float* a_src1 = (const float*)d_in[3];
    const float* a_dst1 = (const float*)d_in[4];
    const float* b1     = (const float*)d_in[5];
    const float* W2     = (const float*)d_in[6];
    const float* a_src2 = (const float*)d_in[7];
    const float* a_dst2 = (const float*)d_in[8];
    const float* b2     = (const float*)d_in[9];
    float*       out    = (float*)d_out;

    const int n = in_sizes[0] / IND;      // 50000
    const int E = in_sizes[1] / 2;        // 800000
    const int tot = E + n;

    const int nb256 = (n + 255) / 256;
    const int eb256 = (tot + 255) / 256;
    const int nscan = (n + 1023) / 1024;

    // 0: fused prep (x frag split + W frag split + zero)
    {
        const int np128 = ((n + 127) / 128) * 128;     // 50048
        const int xwb = (np128 / 16) * (IND / 16);     // A-frag warp blocks
        const int xblocks = (xwb + 7) / 8;
        const int zblocks = (n * NHEADS + 255) / 256;
        prep_kernel<<<xblocks + 80 + zblocks, 256>>>(x, W1, W2, n, xwb);
    }
    // 1: histogram
    hist_kernel<<<eb256, 256>>>(ei, E, n);
    // 2: scan1
    scan1_kernel<<<nscan, 1024>>>(n);
    // 3: GEMM1 (+ fused alpha1)  <- ncu captures this index
    {
        dim3 grid(D1 / 64, (n + 127) / 128);
        mma_gemm_kernel<1><<<grid, 256>>>(n, a_src1, a_dst1);
    }
    // 4-6: scan2/scan3/scatter
    scan2_kernel<<<1, 64>>>(nscan, n);
    scan3_kernel<<<nb256, 256>>>(n);
    scatter_kernel<<<eb256, 256>>>(ei, E, n);
    // 7: aggregation layer 1 (frag-order hr output)
    {
        const int grid = (n + 15) / 16;
        agg_kernel<NHEADS, 8, true, 16><<<grid, 16 * 32>>>(b1, nullptr, n);
    }
    // 8: GEMM2 (+ fused alpha2)
    {
        dim3 grid(D2 / 64, (n + 127) / 128);
        mma_gemm_kernel<2><<<grid, 256>>>(n, a_src2, a_dst2);
    }
    // 9: aggregation layer 2 -> out
    {
        const int grid = (n + 7) / 8;
        agg_kernel<1, 2, false, 8><<<grid, 8 * 32>>>(b2, out, n);
    }
}

// round 15
// speedup vs baseline: 1.3641x; 1.0859x over previous
#include <cuda_runtime.h>
#include <cuda_bf16.h>
#include <cuda_fp16.h>
#include <cstdint>
#include <cmath>

// Problem constants (match reference_code)
#define NN     50000
#define NNP    50048   // NN padded to multiple of 128 (frag-ordered A arrays)
#define EE     800000
#define ETOT   (NN + EE)
#define IND    256
#define HIDD   64
#define NHEADS 4
#define D1     256
#define D2     64
#define NEG_SLOPE 0.2f

// ---------------------------------------------------------------------------
// Scratch.  A-side arrays (g_xh/g_xl/g_hrh/g_hrl) in MMA A-FRAGMENT ORDER:
//   16x16 block (rb,kb): offset = (rb*(K/16)+kb)*256 + lane*8 + q*2 + e
// W arrays in MMA B-FRAGMENT ORDER:
//   8x16 block (nb8,kbb): offset = (nb8*(K/16)+kbb)*128 + lane*4 + reg*2 + e
// h1/h2 (gathered by aggregation) stored fp16 to halve gather bytes.
// ---------------------------------------------------------------------------
__device__ __align__(16) __half g_h1[(size_t)NN * D1];
__device__ __align__(16) __half g_h2[(size_t)NN * D2];
__device__ __align__(16) __nv_bfloat16 g_xh[(size_t)NNP * IND];
__device__ __align__(16) __nv_bfloat16 g_xl[(size_t)NNP * IND];
__device__ __align__(16) __nv_bfloat16 g_w1h[IND * D1];
__device__ __align__(16) __nv_bfloat16 g_w1l[IND * D1];
__device__ __align__(16) __nv_bfloat16 g_w2h[D1 * D2];
__device__ __align__(16) __nv_bfloat16 g_w2l[D1 * D2];
__device__ __align__(16) __nv_bfloat16 g_hrh[(size_t)NNP * D1];
__device__ __align__(16) __nv_bfloat16 g_hrl[(size_t)NNP * D1];
__device__ __align__(16) float g_as1[NN * NHEADS];
__device__ __align__(16) float g_ad1[NN * NHEADS];
__device__ __align__(16) float g_as2[NN];
__device__ __align__(16) float g_ad2[NN];
__device__ int   g_deg[NN];
__device__ int   g_row[NN + 1];
__device__ int   g_cur[NN];
__device__ int   g_csr[ETOT];
__device__ int   g_bsum[64];
__device__ int   g_boff[64];

// ---------------------------------------------------------------------------
// helpers
// ---------------------------------------------------------------------------
__device__ __forceinline__ void mma16816(float* c, const uint32_t* a, const uint32_t* b) {
    asm volatile(
        "mma.sync.aligned.m16n8k16.row.col.f32.bf16.bf16.f32 "
        "{%0,%1,%2,%3},{%4,%5,%6,%7},{%8,%9},{%0,%1,%2,%3};"
        : "+f"(c[0]), "+f"(c[1]), "+f"(c[2]), "+f"(c[3])
        : "r"(a[0]), "r"(a[1]), "r"(a[2]), "r"(a[3]), "r"(b[0]), "r"(b[1]));
}
__device__ __forceinline__ __nv_bfloat162 split2(float2 v, __nv_bfloat162* lo) {
    const __nv_bfloat16 h0 = __float2bfloat16(v.x);
    const __nv_bfloat16 h1 = __float2bfloat16(v.y);
    lo->x = __float2bfloat16(v.x - __bfloat162float(h0));
    lo->y = __float2bfloat16(v.y - __bfloat162float(h1));
    return __nv_bfloat162{h0, h1};
}
__device__ __forceinline__ uint32_t b2u(__nv_bfloat162 v) {
    return *reinterpret_cast<uint32_t*>(&v);
}

// ---------------------------------------------------------------------------
// prep: x -> A-frag bf16 hi/lo, W1/W2 -> B-frag bf16 hi/lo, zero accumulators.
// ---------------------------------------------------------------------------
__global__ void prep_kernel(const float* __restrict__ x,
                            const float* __restrict__ W1,
                            const float* __restrict__ W2,
                            int n, int xwb)
{
    const int xblocks = (xwb + 7) >> 3;
    const int bid = blockIdx.x;
    const int lane = threadIdx.x & 31;

    if (bid < xblocks) {
        const int wb = bid * 8 + (threadIdx.x >> 5);
        if (wb >= xwb) return;
        const int rb = wb >> 4;
        const int kb = wb & 15;
        const int r0 = rb * 16 + (lane >> 2);
        const int r1 = r0 + 8;
        const int c  = kb * 16 + ((lane & 3) << 1);

        const float2 z = make_float2(0.f, 0.f);
        const float2 a0 = (r0 < n) ? *reinterpret_cast<const float2*>(x + (size_t)r0 * IND + c)     : z;
        const float2 a1 = (r0 < n) ? *reinterpret_cast<const float2*>(x + (size_t)r0 * IND + c + 8) : z;
        const float2 b0 = (r1 < n) ? *reinterpret_cast<const float2*>(x + (size_t)r1 * IND + c)     : z;
        const float2 b1 = (r1 < n) ? *reinterpret_cast<const float2*>(x + (size_t)r1 * IND + c + 8) : z;

        __nv_bfloat162 h[4], l[4];
        h[0] = split2(a0, &l[0]);
        h[1] = split2(b0, &l[1]);
        h[2] = split2(a1, &l[2]);
        h[3] = split2(b1, &l[3]);

        const size_t off = (size_t)wb * 256 + lane * 8;
        *reinterpret_cast<uint4*>(g_xh + off) = *reinterpret_cast<uint4*>(h);
        *reinterpret_cast<uint4*>(g_xl + off) = *reinterpret_cast<uint4*>(l);
        return;
    }

    int b2 = bid - xblocks;
    if (b2 < 80) {
        const int widx = b2 * 8 + (threadIdx.x >> 5);   // 0..639
        if (widx >= 640) return;
        const float* W;
        __nv_bfloat16 *dh, *dl;
        int Nn, blkid;
        if (widx < 512) { W = W1; dh = g_w1h; dl = g_w1l; Nn = D1; blkid = widx; }
        else            { W = W2; dh = g_w2h; dl = g_w2l; Nn = D2; blkid = widx - 512; }
        const int nb8 = blkid >> 4, kbb = blkid & 15;
        const int nn = nb8 * 8 + (lane >> 2);
        const int k0 = kbb * 16 + (lane & 3) * 2;
        const float w00 = W[(size_t)k0 * Nn + nn];
        const float w01 = W[(size_t)(k0 + 1) * Nn + nn];
        const float w10 = W[(size_t)(k0 + 8) * Nn + nn];
        const float w11 = W[(size_t)(k0 + 9) * Nn + nn];
        __nv_bfloat162 l0, l1;
        const __nv_bfloat162 h0 = split2(make_float2(w00, w01), &l0);
        const __nv_bfloat162 h1 = split2(make_float2(w10, w11), &l1);
        *reinterpret_cast<uint2*>(dh + (size_t)blkid * 128 + lane * 4) = make_uint2(b2u(h0), b2u(h1));
        *reinterpret_cast<uint2*>(dl + (size_t)blkid * 128 + lane * 4) = make_uint2(b2u(l0), b2u(l1));
        return;
    }

    const int i = (b2 - 80) * 256 + threadIdx.x;
    if (i < n) {
        g_deg[i] = 0;
        g_as2[i] = 0.f;
        g_ad2[i] = 0.f;
    }
    if (i < n * NHEADS) {
        g_as1[i] = 0.f;
        g_ad1[i] = 0.f;
    }
}

// ---------------------------------------------------------------------------
// Tensor-core GEMM (bf16 3-term split), NO shared memory, no barriers.
// A and B fragments direct from frag-ordered global.  C output in fp16.
// 128x64 CTA tile, 8 warps (4m x 2n), 2 CTAs/SM.  Fused alpha-dot epilogue.
// ---------------------------------------------------------------------------
template <int LAYER>
__global__ void __launch_bounds__(256, 2)
mma_gemm_kernel(int M, const float* __restrict__ avec_s,
                const float* __restrict__ avec_d)
{
    constexpr int K  = 256;
    constexpr int N  = (LAYER == 1) ? D1 : D2;
    constexpr int NT = 4;

    const __nv_bfloat16* __restrict__ Ah = (LAYER == 1) ? g_xh  : g_hrh;
    const __nv_bfloat16* __restrict__ Al = (LAYER == 1) ? g_xl  : g_hrl;
    const __nv_bfloat16* __restrict__ Bh = (LAYER == 1) ? g_w1h : g_w2h;
    const __nv_bfloat16* __restrict__ Bl = (LAYER == 1) ? g_w1l : g_w2l;
    __half* __restrict__ C               = (LAYER == 1) ? g_h1  : g_h2;
    float* __restrict__ as_out           = (LAYER == 1) ? g_as1 : g_as2;
    float* __restrict__ ad_out           = (LAYER == 1) ? g_ad1 : g_ad2;

    const int tid  = threadIdx.x;
    const int lane = tid & 31;
    const int wid  = tid >> 5;
    const int wm   = (wid & 3) * 32;
    const int wn   = (wid >> 2) * 32;
    const int brow = blockIdx.y * 128;
    const int bcol = blockIdx.x * 64;

    const __nv_bfloat16* aph[2];
    const __nv_bfloat16* apl[2];
#pragma unroll
    for (int i = 0; i < 2; i++) {
        const int rb = (brow + wm + i * 16) >> 4;
        aph[i] = Ah + (size_t)rb * (K / 16) * 256 + lane * 8;
        apl[i] = Al + (size_t)rb * (K / 16) * 256 + lane * 8;
    }
    const int nb8base = (bcol + wn) >> 3;
    const __nv_bfloat16* bph = Bh + (size_t)nb8base * (K / 16) * 128 + lane * 4;
    const __nv_bfloat16* bpl = Bl + (size_t)nb8base * (K / 16) * 128 + lane * 4;

    uint4 abh[2][2][2], abl[2][2][2];   // [buf][ks][i]
    auto aload = [&](int kt, int buf) {
#pragma unroll
        for (int ks = 0; ks < 2; ks++) {
            const int kb = kt * 2 + ks;
#pragma unroll
            for (int i = 0; i < 2; i++) {
                abh[buf][ks][i] = *reinterpret_cast<const uint4*>(aph[i] + kb * 256);
                abl[buf][ks][i] = *reinterpret_cast<const uint4*>(apl[i] + kb * 256);
            }
        }
    };

    float c[2][NT][4];
#pragma unroll
    for (int i = 0; i < 2; i++)
#pragma unroll
        for (int j = 0; j < NT; j++)
#pragma unroll
            for (int q = 0; q < 4; q++) c[i][j][q] = 0.f;

    aload(0, 0);

#pragma unroll
    for (int kt = 0; kt < K / 32; kt++) {
        if (kt + 1 < K / 32) aload(kt + 1, (kt + 1) & 1);
        const int bf = kt & 1;
#pragma unroll
        for (int ks = 0; ks < 2; ks++) {
            const int kbb = kt * 2 + ks;
            uint2 fbh[NT], fbl[NT];
#pragma unroll
            for (int j = 0; j < NT; j++) {
                fbh[j] = *reinterpret_cast<const uint2*>(bph + j * (K / 16) * 128 + kbb * 128);
                fbl[j] = *reinterpret_cast<const uint2*>(bpl + j * (K / 16) * 128 + kbb * 128);
            }
#pragma unroll
            for (int i = 0; i < 2; i++) {
                const uint32_t* fah = reinterpret_cast<const uint32_t*>(&abh[bf][ks][i]);
                const uint32_t* fal = reinterpret_cast<const uint32_t*>(&abl[bf][ks][i]);
#pragma unroll
                for (int j = 0; j < NT; j++) {
                    mma16816(c[i][j], fah, reinterpret_cast<const uint32_t*>(&fbh[j]));
                    mma16816(c[i][j], fah, reinterpret_cast<const uint32_t*>(&fbl[j]));
                    mma16816(c[i][j], fal, reinterpret_cast<const uint32_t*>(&fbh[j]));
                }
            }
        }
    }

    // ---- epilogue: store C (fp16) + fused (partial) alpha dots ----
    const int head = (LAYER == 1) ? (bcol >> 6) : 0;
#pragma unroll
    for (int i = 0; i < 2; i++) {
        float s0 = 0.f, s1 = 0.f, d0 = 0.f, d1 = 0.f;
#pragma unroll
        for (int j = 0; j < NT; j++) {
            const int col = bcol + wn + j * 8 + (lane & 3) * 2;
            const float a0 = __ldg(avec_s + col), a1 = __ldg(avec_s + col + 1);
            const float b0 = __ldg(avec_d + col), b1 = __ldg(avec_d + col + 1);
            s0 += c[i][j][0] * a0 + c[i][j][1] * a1;
            s1 += c[i][j][2] * a0 + c[i][j][3] * a1;
            d0 += c[i][j][0] * b0 + c[i][j][1] * b1;
            d1 += c[i][j][2] * b0 + c[i][j][3] * b1;

            const int r = brow + wm + i * 16 + (lane >> 2);
            if (r < M)
                *reinterpret_cast<__half2*>(C + (size_t)r * N + col) =
                    __floats2half2_rn(c[i][j][0], c[i][j][1]);
            if (r + 8 < M)
                *reinterpret_cast<__half2*>(C + (size_t)(r + 8) * N + col) =
                    __floats2half2_rn(c[i][j][2], c[i][j][3]);
        }
#pragma unroll
        for (int off = 1; off <= 2; off <<= 1) {
            s0 += __shfl_xor_sync(0xffffffffu, s0, off);
            s1 += __shfl_xor_sync(0xffffffffu, s1, off);
            d0 += __shfl_xor_sync(0xffffffffu, d0, off);
            d1 += __shfl_xor_sync(0xffffffffu, d1, off);
        }
        if ((lane & 3) == 0) {
            const int r = brow + wm + i * 16 + (lane >> 2);
            const int stride = (LAYER == 1) ? NHEADS : 1;
            if (r < M) {
                atomicAdd(&as_out[r * stride + head], s0);
                atomicAdd(&ad_out[r * stride + head], d0);
            }
            if (r + 8 < M) {
                atomicAdd(&as_out[(r + 8) * stride + head], s1);
                atomicAdd(&ad_out[(r + 8) * stride + head], d1);
            }
        }
    }
}

// ---------------------------------------------------------------------------
// CSR build
// ---------------------------------------------------------------------------
__global__ void hist_kernel(const int* __restrict__ ei, int E, int n)
{
    const int i = blockIdx.x * blockDim.x + threadIdx.x;
    const int tot = E + n;
    if (i >= tot) return;
    const int d = (i < E) ? ei[E + i] : (i - E);
    if ((unsigned)d < (unsigned)n)
        atomicAdd(&g_deg[d], 1);
}

__global__ void scan1_kernel(int n)
{
    __shared__ int smem[1024];
    const int tid = threadIdx.x;
    const int i = blockIdx.x * 1024 + tid;
    const int v = (i < n) ? g_deg[i] : 0;
    int x = v;
#pragma unroll
    for (int off = 1; off < 1024; off <<= 1) {
        smem[tid] = x;
        __syncthreads();
        if (tid >= off) x += smem[tid - off];
        __syncthreads();
    }
    if (i < n) g_row[i] = x - v;
    if (tid == 1023) g_bsum[blockIdx.x] = x;
}

__global__ void scan2_kernel(int nb, int n)
{
    __shared__ int sm[64];
    const int tid = threadIdx.x;
    const int v = (tid < nb) ? g_bsum[tid] : 0;
    int x = v;
#pragma unroll
    for (int off = 1; off < 64; off <<= 1) {
        sm[tid] = x;
        __syncthreads();
        if (tid >= off) x += sm[tid - off];
        __syncthreads();
    }
    if (tid < nb) g_boff[tid] = x - v;
    if (tid == 63) g_row[n] = x;
}

__global__ void scan3_kernel(int n)
{
    const int i = blockIdx.x * blockDim.x + threadIdx.x;
    if (i >= n) return;
    const int v = g_row[i] + g_boff[i >> 10];
    g_row[i] = v;
    g_cur[i] = v;
}

__global__ void scatter_kernel(const int* __restrict__ ei, int E, int n)
{
    const int i = blockIdx.x * blockDim.x + threadIdx.x;
    const int tot = E + n;
    if (i >= tot) return;
    int s, d;
    if (i < E) {
        s = ei[i];
        d = ei[E + i];
    } else {
        s = d = i - E;
    }
    if ((unsigned)d < (unsigned)n && (unsigned)s < (unsigned)n) {
        const int pos = atomicAdd(&g_cur[d], 1);
        if ((unsigned)pos < (unsigned)ETOT)
            g_csr[pos] = s;
    }
}

// ---------------------------------------------------------------------------
// GAT aggregation, warp-per-destination (2-pass softmax, chunked gather).
// h matrices are fp16 (half the gather bytes); fp32 accumulation.
// L1: NW=16 rows/block; frag-order bf16 hi/lo output staged via smem.
// L2: NW=8, fp32 out.
// ---------------------------------------------------------------------------
#define AGG_WARPS 8

template <int HEADS, int RP, bool L1, int NW>
__global__ void __launch_bounds__(NW * 32)
agg_kernel(const float* __restrict__ bias,
           float* __restrict__ out_ext, int n)
{
    constexpr int D = RP * 32;
    const __half* __restrict__ h = L1 ? g_h1  : g_h2;
    const float* __restrict__ as = L1 ? g_as1 : g_as2;
    const float* __restrict__ ad = L1 ? g_ad1 : g_ad2;

    __shared__ int   s_src[NW][32];
    __shared__ float s_w[NW][32][HEADS];
    __shared__ __align__(16) __nv_bfloat16 st_h[L1 ? 16 * 264 : 1];
    __shared__ __align__(16) __nv_bfloat16 st_l[L1 ? 16 * 264 : 1];

    const int wslot = threadIdx.x >> 5;
    const int lane  = threadIdx.x & 31;
    const int warp  = blockIdx.x * NW + wslot;
    const bool valid = warp < n;
    if (!L1 && !valid) return;

    int start = 0, end = 0;
    if (valid) {
        start = g_row[warp];
        end   = g_row[warp + 1];
    }

    float adv[HEADS];
#pragma unroll
    for (int hh = 0; hh < HEADS; hh++)
        adv[hh] = valid ? ad[warp * HEADS + hh] : 0.f;

    // ---- pass A: sum of exp ----
    float ssum[HEADS];
#pragma unroll
    for (int hh = 0; hh < HEADS; hh++) ssum[hh] = 0.f;
    for (int i = start + lane; i < end; i += 32) {
        const int s = g_csr[i];
#pragma unroll
        for (int hh = 0; hh < HEADS; hh++) {
            float e = as[s * HEADS + hh] + adv[hh];
            e = (e >= 0.f) ? e : NEG_SLOPE * e;
            ssum[hh] += __expf(e);
        }
    }
#pragma unroll
    for (int hh = 0; hh < HEADS; hh++) {
#pragma unroll
        for (int off = 16; off > 0; off >>= 1)
            ssum[hh] += __shfl_xor_sync(0xffffffffu, ssum[hh], off);
    }
    float inv[HEADS];
#pragma unroll
    for (int hh = 0; hh < HEADS; hh++) inv[hh] = 1.0f / ssum[hh];

    // ---- pass B: chunked weighted gather-accumulate (fp16 loads) ----
    const int head = (lane * RP) >> 6;
    float acc[RP];
#pragma unroll
    for (int r = 0; r < RP; r++) acc[r] = 0.f;

    for (int base = start; base < end; base += 32) {
        const int cnt = min(32, end - base);
        const int i = base + lane;
        if (lane < cnt) {
            const int s = g_csr[i];
            s_src[wslot][lane] = s;
#pragma unroll
            for (int hh = 0; hh < HEADS; hh++) {
                float e = as[s * HEADS + hh] + adv[hh];
                e = (e >= 0.f) ? e : NEG_SLOPE * e;
                s_w[wslot][lane][hh] = __expf(e) * inv[hh];
            }
        }
        __syncwarp();

#pragma unroll 2
        for (int j = 0; j < cnt; j++) {
            const int s   = s_src[wslot][j];
            const float w = s_w[wslot][j][head];
            const __half* rowp = h + (size_t)s * D + lane * RP;
            if constexpr (RP == 8) {
                const uint4 v = *reinterpret_cast<const uint4*>(rowp);
                const __half2* hv = reinterpret_cast<const __half2*>(&v);
                const float2 f0 = __half22float2(hv[0]);
                const float2 f1 = __half22float2(hv[1]);
                const float2 f2 = __half22float2(hv[2]);
                const float2 f3 = __half22float2(hv[3]);
                acc[0] += w * f0.x; acc[1] += w * f0.y;
                acc[2] += w * f1.x; acc[3] += w * f1.y;
                acc[4] += w * f2.x; acc[5] += w * f2.y;
                acc[6] += w * f3.x; acc[7] += w * f3.y;
            } else {
                const float2 f0 = __half22float2(
                    *reinterpret_cast<const __half2*>(rowp));
                acc[0] += w * f0.x; acc[1] += w * f0.y;
            }
        }
        __syncwarp();
    }

    // ---- epilogue ----
#pragma unroll
    for (int r = 0; r < RP; r++) {
        float v = acc[r] + bias[lane * RP + r];
        if (L1) v = fmaxf(v, 0.f);
        acc[r] = v;
    }
    if constexpr (L1) {
        if (valid) {
            const int lr = wslot;
            const int kb = lane >> 1;
            const int q  = ((lr >> 3) & 1) | ((lane & 1) << 1);
#pragma unroll
            for (int t = 0; t < 4; t++) {
                __nv_bfloat162 lo2;
                const __nv_bfloat162 hi2 = split2(make_float2(acc[2 * t], acc[2 * t + 1]), &lo2);
                const int o = kb * 264 + (((lr & 7) << 2) + t) * 8 + q * 2;
                *reinterpret_cast<__nv_bfloat162*>(st_h + o) = hi2;
                *reinterpret_cast<__nv_bfloat162*>(st_l + o) = lo2;
            }
        }
        __syncthreads();
        const int t = threadIdx.x;
        const int kb = t >> 5, inner = t & 31;
        const uint4 vh = *reinterpret_cast<const uint4*>(st_h + kb * 264 + inner * 8);
        const uint4 vl = *reinterpret_cast<const uint4*>(st_l + kb * 264 + inner * 8);
        const size_t off = ((size_t)(blockIdx.x * 16 + kb)) * 256 + inner * 8;
        *reinterpret_cast<uint4*>(g_hrh + off) = vh;
        *reinterpret_cast<uint4*>(g_hrl + off) = vl;
    } else {
        float* op = out_ext + (size_t)warp * D + lane * RP;
        *reinterpret_cast<float2*>(op) = make_float2(acc[0], acc[1]);
    }
}

// ---------------------------------------------------------------------------
// Launch — kernel launches ONLY.  GEMM1 at captured index 3.
// ---------------------------------------------------------------------------
extern "C" void kernel_launch(void* const* d_in, const int* in_sizes, int n_in,
                              void* d_out, int out_size)
{
    const float* x      = (const float*)d_in[0];
    const int*   ei     = (const int*)d_in[1];   // int32 (JAX x64 disabled)
    const float* W1     = (const float*)d_in[2];
    const float* a_src1 = (const float*)d_in[3];
    const float* a_dst1 = (const float*)d_in[4];
    const float* b1     = (const float*)d_in[5];
    const float* W2     = (const float*)d_in[6];
    const float* a_src2 = (const float*)d_in[7];
    const float* a_dst2 = (const float*)d_in[8];
    const float* b2     = (const float*)d_in[9];
    float*       out    = (float*)d_out;

    const int n = in_sizes[0] / IND;      // 50000
    const int E = in_sizes[1] / 2;        // 800000
    const int tot = E + n;

    const int nb256 = (n + 255) / 256;
    const int eb256 = (tot + 255) / 256;
    const int nscan = (n + 1023) / 1024;

    // 0: fused prep (x frag split + W frag split + zero)
    {
        const int np128 = ((n + 127) / 128) * 128;     // 50048
        const int xwb = (np128 / 16) * (IND / 16);
        const int xblocks = (xwb + 7) / 8;
        const int zblocks = (n * NHEADS + 255) / 256;
        prep_kernel<<<xblocks + 80 + zblocks, 256>>>(x, W1, W2, n, xwb);
    }
    // 1: histogram
    hist_kernel<<<eb256, 256>>>(ei, E, n);
    // 2: scan1
    scan1_kernel<<<nscan, 1024>>>(n);
    // 3: GEMM1 (+ fused alpha1)  <- ncu captures this index
    {
        dim3 grid(D1 / 64, (n + 127) / 128);
        mma_gemm_kernel<1><<<grid, 256>>>(n, a_src1, a_dst1);
    }
    // 4-6: scan2/scan3/scatter
    scan2_kernel<<<1, 64>>>(nscan, n);
    scan3_kernel<<<nb256, 256>>>(n);
    scatter_kernel<<<eb256, 256>>>(ei, E, n);
    // 7: aggregation layer 1 (fp16 gathers, frag-order hr output)
    {
        const int grid = (n + 15) / 16;
        agg_kernel<NHEADS, 8, true, 16><<<grid, 16 * 32>>>(b1, nullptr, n);
    }
    // 8: GEMM2 (+ fused alpha2)
    {
        dim3 grid(D2 / 64, (n + 127) / 128);
        mma_gemm_kernel<2><<<grid, 256>>>(n, a_src2, a_dst2);
    }
    // 9: aggregation layer 2 -> out
    {
        const int grid = (n + 7) / 8;
        agg_kernel<1, 2, false, 8><<<grid, 8 * 32>>>(b2, out, n);
    }
}